// round 12
// baseline (speedup 1.0000x reference)
#include <cuda_runtime.h>
#include <cuda_fp16.h>
#include <math.h>
#include <stdint.h>

#define C_      512
#define S_      8192
#define HW_     1024
#define W_      32
#define NGROUP  32
#define CPG     16
#define KC      13824
#define NSPLIT  4
#define KSPLIT_ITERS 108      // (KC/32)/4
#define KSUM_BLOCKS 4096      // (C_*S_/4)/256

// attention smem stage: A 8K | B 8K
#define STG 16384
// conv smem stage: A 8K | B 16K (CTA 128x256)
#define CSTG 24576

typedef unsigned short ushort_t;

__device__ float g_mean[NGROUP];
__device__ float g_rstd[NGROUP];
__device__ float2 g_part[KSUM_BLOCKS];
__device__ float g_t1 [(size_t)C_ * S_];
__device__ float g_y0 [(size_t)C_ * S_];
__device__ float g_mid[(size_t)C_ * S_];
__device__ float g_p  [(size_t)S_ * S_];
__device__ float g_ks [(size_t)NSPLIT * C_ * S_];
// fp16 operands
__device__ __align__(16) ushort_t g_ath[(size_t)S_ * C_];    // normalized act [s][c]
__device__ __align__(16) ushort_t g_wh [(size_t)C_ * KC];    // conv weights, K = r*512+ci
__device__ __align__(16) ushort_t g_wah[(size_t)C_ * C_];
__device__ __align__(16) ushort_t g_qh [(size_t)S_ * C_];
__device__ __align__(16) ushort_t g_kh [(size_t)S_ * C_];
__device__ __align__(16) ushort_t g_vh [(size_t)C_ * S_];
__device__ __align__(16) ushort_t g_oh [(size_t)S_ * C_];
__device__ __align__(16) ushort_t g_ph [(size_t)S_ * S_];

// ---------------- PTX helpers ----------------
__device__ __forceinline__ uint32_t smem_u32(const void* p) {
    uint32_t a;
    asm("{ .reg .u64 t; cvta.to.shared.u64 t, %1; cvt.u32.u64 %0, t; }" : "=r"(a) : "l"(p));
    return a;
}
#define CP_ASYNC16(smem, gmem) \
    asm volatile("cp.async.cg.shared.global [%0], [%1], 16;" :: "r"(smem), "l"(gmem) : "memory")
#define CP_COMMIT() asm volatile("cp.async.commit_group;" ::: "memory")
#define CP_WAIT1()  asm volatile("cp.async.wait_group 1;" ::: "memory")
#define CP_WAIT2()  asm volatile("cp.async.wait_group 2;" ::: "memory")
#define LDSM4(r, addr) \
    asm volatile("ldmatrix.sync.aligned.m8n8.x4.shared.b16 {%0,%1,%2,%3}, [%4];" \
        : "=r"((r)[0]),"=r"((r)[1]),"=r"((r)[2]),"=r"((r)[3]) : "r"(addr))
#define MMA16816(d, a, b0, b1) \
    asm volatile("mma.sync.aligned.m16n8k16.row.col.f32.f16.f16.f32 " \
        "{%0,%1,%2,%3}, {%4,%5,%6,%7}, {%8,%9}, {%0,%1,%2,%3};" \
        : "+f"((d)[0]),"+f"((d)[1]),"+f"((d)[2]),"+f"((d)[3]) \
        : "r"((a)[0]),"r"((a)[1]),"r"((a)[2]),"r"((a)[3]), "r"(b0),"r"(b1))

__device__ __forceinline__ ushort_t to_h(float v) {
    return __half_as_ushort(__float2half_rn(v));
}

__inline__ __device__ float warp_sum(float v) {
    #pragma unroll
    for (int o = 16; o; o >>= 1) v += __shfl_down_sync(0xffffffffu, v, o);
    return v;
}
__inline__ __device__ float warp_max(float v) {
    #pragma unroll
    for (int o = 16; o; o >>= 1) v = fmaxf(v, __shfl_down_sync(0xffffffffu, v, o));
    return v;
}

// ---------------- GroupNorm stats (full read) ----------------
__global__ void gn_stats_k(const float* __restrict__ x) {
    int g = blockIdx.x;
    const float4* p = (const float4*)(x + (size_t)g * CPG * S_);
    const int n4 = (CPG * S_) / 4;
    float s = 0.f, s2 = 0.f;
    for (int i = threadIdx.x; i < n4; i += blockDim.x) {
        float4 v = p[i];
        s  += v.x + v.y + v.z + v.w;
        s2 += v.x * v.x + v.y * v.y + v.z * v.z + v.w * v.w;
    }
    __shared__ float sh0[8], sh1[8];
    float ws = warp_sum(s), ws2 = warp_sum(s2);
    int wid = threadIdx.x >> 5, lid = threadIdx.x & 31;
    if (!lid) { sh0[wid] = ws; sh1[wid] = ws2; }
    __syncthreads();
    if (threadIdx.x == 0) {
        float a = 0.f, b = 0.f;
        #pragma unroll
        for (int i = 0; i < 8; i++) { a += sh0[i]; b += sh1[i]; }
        const float inv_n = 1.f / (float)(CPG * S_);
        float m = a * inv_n;
        g_mean[g] = m;
        g_rstd[g] = rsqrtf(b * inv_n - m * m + 1e-6f);
    }
}

// ---------------- GroupNorm stats from ksum partials ----------------
__global__ void gn_stats_p() {
    int g = blockIdx.x;
    float2 v = g_part[g * 128 + threadIdx.x];
    __shared__ float sh0[4], sh1[4];
    float ws = warp_sum(v.x), ws2 = warp_sum(v.y);
    int wid = threadIdx.x >> 5, lid = threadIdx.x & 31;
    if (!lid) { sh0[wid] = ws; sh1[wid] = ws2; }
    __syncthreads();
    if (threadIdx.x == 0) {
        float a = sh0[0] + sh0[1] + sh0[2] + sh0[3];
        float b = sh1[0] + sh1[1] + sh1[2] + sh1[3];
        const float inv_n = 1.f / (float)(CPG * S_);
        float m = a * inv_n;
        g_mean[g] = m;
        g_rstd[g] = rsqrtf(b * inv_n - m * m + 1e-6f);
    }
}

// ---------------- transposing GN (+optional SiLU): x [c][s] -> fp16 [s][c] ------
__global__ void normact_t_k(const float* __restrict__ x, const float* __restrict__ sc,
                            const float* __restrict__ bi, int do_silu) {
    __shared__ float tile[32][33];
    int s0 = blockIdx.x * 32, c0 = blockIdx.y * 32;
    int tx = threadIdx.x, ty = threadIdx.y;
    #pragma unroll
    for (int i = ty; i < 32; i += 8)
        tile[i][tx] = x[(size_t)(c0 + i) * S_ + s0 + tx];
    __syncthreads();
    int c = c0 + tx;
    int g = c >> 4;
    float mu = g_mean[g], rs = g_rstd[g], sv = sc[c], bv = bi[c];
    #pragma unroll
    for (int i = ty; i < 32; i += 8) {
        float v = (tile[tx][i] - mu) * rs * sv + bv;
        if (do_silu) v = v / (1.f + __expf(-v));
        g_ath[(size_t)(s0 + i) * C_ + c] = to_h(v);
    }
}

// ---------------- conv weight pack: w[co][ci*27+r] -> fp16 g_wh[co][r*512+ci] ----
__global__ void wpack_conv_k(const float* __restrict__ w) {
    size_t id = (size_t)blockIdx.x * 256 + threadIdx.x;
    int co = (int)(id / 1728);
    int kk = (int)(id - (size_t)co * 1728) * 8;
    int r  = kk >> 9;
    int ci0 = kk & 511;
    const float* src = w + (size_t)co * KC + r;
    __align__(16) ushort_t hv[8];
    #pragma unroll
    for (int e = 0; e < 8; e++)
        hv[e] = to_h(src[(size_t)(ci0 + e) * 27]);
    *(uint4*)(g_wh + (size_t)co * KC + kk) = *(uint4*)hv;
}

// ---------------- pack: fp32 row-major -> fp16 (attention weights) ----------------
__global__ void wpack_k(const float* __restrict__ w, ushort_t* __restrict__ dh) {
    size_t id = (size_t)blockIdx.x * 256 + threadIdx.x;
    const float4* src = (const float4*)w;
    float4 v0 = src[id * 2], v1 = src[id * 2 + 1];
    __align__(16) ushort_t hv[8];
    hv[0] = to_h(v0.x); hv[1] = to_h(v0.y); hv[2] = to_h(v0.z); hv[3] = to_h(v0.w);
    hv[4] = to_h(v1.x); hv[5] = to_h(v1.y); hv[6] = to_h(v1.z); hv[7] = to_h(v1.w);
    *(uint4*)(dh + id * 8) = *(uint4*)hv;
}

// ---------------- split-K reduce + per-block GN partials ----------------
__global__ void ksum_k(float* __restrict__ out, const float* __restrict__ bias,
                       const float* __restrict__ addend) {
    size_t i = ((size_t)blockIdx.x * 256 + threadIdx.x) * 4;
    int c = (int)(i >> 13);
    float4 v0 = *(const float4*)(g_ks + i);
    float4 v1 = *(const float4*)(g_ks + (size_t)C_ * S_ + i);
    float4 v2 = *(const float4*)(g_ks + (size_t)2 * C_ * S_ + i);
    float4 v3 = *(const float4*)(g_ks + (size_t)3 * C_ * S_ + i);
    float bv = bias[c];
    float4 r;
    r.x = v0.x + v1.x + v2.x + v3.x + bv;
    r.y = v0.y + v1.y + v2.y + v3.y + bv;
    r.z = v0.z + v1.z + v2.z + v3.z + bv;
    r.w = v0.w + v1.w + v2.w + v3.w + bv;
    if (addend) {
        float4 a = *(const float4*)(addend + i);
        r.x += a.x; r.y += a.y; r.z += a.z; r.w += a.w;
    }
    *(float4*)(out + i) = r;
    float s  = r.x + r.y + r.z + r.w;
    float s2 = r.x * r.x + r.y * r.y + r.z * r.z + r.w * r.w;
    __shared__ float sh0[8], sh1[8];
    float ws = warp_sum(s), ws2 = warp_sum(s2);
    int wid = threadIdx.x >> 5, lid = threadIdx.x & 31;
    if (!lid) { sh0[wid] = ws; sh1[wid] = ws2; }
    __syncthreads();
    if (threadIdx.x == 0) {
        float a = 0.f, b = 0.f;
        #pragma unroll
        for (int k = 0; k < 8; k++) { a += sh0[k]; b += sh1[k]; }
        g_part[blockIdx.x] = make_float2(a, b);
    }
}

// ================= attention HMMA mainloop (3-stage, 1 sync/iter) =================
struct HmmaAcc { float a[4][4][4]; };

__device__ __forceinline__ void hmma_mainloop(
    HmmaAcc& A4, uint32_t sm0, int tid,
    const ushort_t* __restrict__ Ah, int lda,
    const ushort_t* __restrict__ Bh, int ldb,
    int m0, int n0, int kiters) {
    const int lane = tid & 31, warp = tid >> 5;
    const int wm = warp & 1, wn = warp >> 1;

    auto issue = [&](int stage, int k0) {
        uint32_t sb = sm0 + stage * STG;
        #pragma unroll
        for (int h = 0; h < 2; h++) {
            int id = tid + h * 256;
            int r = id >> 2, cu = id & 3;
            uint32_t soff = r * 64 + (((cu ^ ((r >> 1) & 3))) << 4);
            CP_ASYNC16(sb + soff,        Ah + (size_t)(m0 + r) * lda + k0 + cu * 8);
            CP_ASYNC16(sb + 8192 + soff, Bh + (size_t)(n0 + r) * ldb + k0 + cu * 8);
        }
        CP_COMMIT();
    };

    issue(0, 0);
    issue(1, 32);

    const int rl = lane & 15, ul = lane >> 4;
    for (int it = 0; it < kiters; it++) {
        CP_WAIT1();
        __syncthreads();
        if (it + 2 < kiters) issue((it + 2) % 3, (it + 2) * 32);
        else CP_COMMIT();
        uint32_t sb = sm0 + (it % 3) * STG;
        #pragma unroll
        for (int k16 = 0; k16 < 2; k16++) {
            uint32_t a4[4][4], b4[2][4];
            int u = k16 * 2 + ul;
            #pragma unroll
            for (int i = 0; i < 4; i++) {
                int r = wm * 64 + i * 16 + rl;
                LDSM4(a4[i], sb + r * 64 + (((u ^ ((r >> 1) & 3))) << 4));
            }
            #pragma unroll
            for (int j2 = 0; j2 < 2; j2++) {
                int r = wn * 32 + j2 * 16 + rl;
                LDSM4(b4[j2], sb + 8192 + r * 64 + (((u ^ ((r >> 1) & 3))) << 4));
            }
            #pragma unroll
            for (int i = 0; i < 4; i++)
                #pragma unroll
                for (int j = 0; j < 4; j++) {
                    int j2 = j >> 1, ts = j & 1;
                    MMA16816(A4.a[i][j], a4[i], b4[j2][ts], b4[j2][ts + 2]);
                }
        }
    }
}

// ---------------- conv GEMM: CTA 128x256, warp tile 64x64, occ1, implicit gather --
// grid (16, 32): x -> m-tile (x&3), ksplit (x>>2); y -> n-tile (256 wide)
__global__ void __launch_bounds__(256, 1) conv_hmma_k() {
    extern __shared__ unsigned char dynsm[];
    const uint32_t sm0 = smem_u32(dynsm);
    const int tid = threadIdx.x, lane = tid & 31, warp = tid >> 5;
    const int m0 = (blockIdx.x & 3) * 128;
    const int ks = blockIdx.x >> 2;
    const int n0 = blockIdx.y * 256;
    const int kbase = ks * (KSPLIT_ITERS * 32);
    const int wm = warp & 1, wn = warp >> 1;   // warp tile: m 64, n 64

    // A loader: 512 chunks, 2/thread. B loader: 1024 chunks, 4/thread.
    int arow[2];
    uint32_t asoff[2];
    #pragma unroll
    for (int h = 0; h < 2; h++) {
        int id = tid + h * 256;
        int r = id >> 2, cu = id & 3;
        arow[h] = r;
        asoff[h] = r * 64 + (((cu ^ ((r >> 1) & 3))) << 4);
    }
    int acu8[2] = { (tid & 3) * 8, (tid & 3) * 8 };
    int brow[4], bcu8[4];
    uint32_t bsoff[4];
    int tm2[4], ym1[4], xm1[4];
    #pragma unroll
    for (int h = 0; h < 4; h++) {
        int id = tid + h * 256;
        int r = id >> 2, cu = id & 3;
        brow[h] = r; bcu8[h] = cu * 8;
        bsoff[h] = r * 64 + (((cu ^ ((r >> 1) & 3))) << 4);
        int pos = n0 + r;
        tm2[h] = (pos >> 10) - 2;
        ym1[h] = ((pos >> 5) & 31) - 1;
        xm1[h] = (pos & 31) - 1;
    }

    auto issue = [&](int stage, int k0) {
        uint32_t sb = sm0 + stage * CSTG;
        int rcode = k0 >> 9;
        int ci0 = k0 & 511;
        int kd = rcode / 9;
        int rr = rcode - kd * 9;
        int kh = rr / 3;
        int kw = rr - kh * 3;
        #pragma unroll
        for (int h = 0; h < 2; h++)
            CP_ASYNC16(sb + asoff[h],
                       g_wh + (size_t)(m0 + arow[h]) * KC + k0 + acu8[h]);
        #pragma unroll
        for (int h = 0; h < 4; h++) {
            int ts = min(max(tm2[h] + kd, 0), 7);
            int ys = min(max(ym1[h] + kh, 0), 31);
            int xs = min(max(xm1[h] + kw, 0), 31);
            CP_ASYNC16(sb + 8192 + bsoff[h],
                       g_ath + (size_t)((ts << 10) + (ys << 5) + xs) * C_ + ci0 + bcu8[h]);
        }
        CP_COMMIT();
    };

    float acc[4][8][4];
    #pragma unroll
    for (int i = 0; i < 4; i++)
        #pragma unroll
        for (int j = 0; j < 8; j++)
            #pragma unroll
            for (int r = 0; r < 4; r++) acc[i][j][r] = 0.f;

    issue(0, kbase);
    issue(1, kbase + 32);
    issue(2, kbase + 64);

    const int rl = lane & 15, ul = lane >> 4;
    for (int it = 0; it < KSPLIT_ITERS; it++) {
        CP_WAIT2();
        __syncthreads();
        if (it + 3 < KSPLIT_ITERS) issue((it + 3) & 3, kbase + (it + 3) * 32);
        else CP_COMMIT();
        uint32_t sb = sm0 + (it & 3) * CSTG;
        #pragma unroll
        for (int k16 = 0; k16 < 2; k16++) {
            uint32_t a4[4][4], b4[4][4];
            int u = k16 * 2 + ul;
            #pragma unroll
            for (int i = 0; i < 4; i++) {
                int r = wm * 64 + i * 16 + rl;
                LDSM4(a4[i], sb + r * 64 + (((u ^ ((r >> 1) & 3))) << 4));
            }
            #pragma unroll
            for (int j2 = 0; j2 < 4; j2++) {
                int r = wn * 64 + j2 * 16 + rl;
                LDSM4(b4[j2], sb + 8192 + r * 64 + (((u ^ ((r >> 1) & 3))) << 4));
            }
            #pragma unroll
            for (int i = 0; i < 4; i++)
                #pragma unroll
                for (int j = 0; j < 8; j++) {
                    int j2 = j >> 1, ts = j & 1;
                    MMA16816(acc[i][j], a4[i], b4[j2][ts], b4[j2][ts + 2]);
                }
        }
    }

    float* Sp = g_ks + (size_t)ks * C_ * S_;
    const int mrow = m0 + wm * 64 + (lane >> 2);
    const int ncol = n0 + wn * 64 + (lane & 3) * 2;
    #pragma unroll
    for (int i = 0; i < 4; i++) {
        int ma = mrow + i * 16, mb = ma + 8;
        #pragma unroll
        for (int j = 0; j < 8; j++) {
            int n = ncol + j * 8;
            *(float2*)(Sp + (size_t)ma * S_ + n) = make_float2(acc[i][j][0], acc[i][j][1]);
            *(float2*)(Sp + (size_t)mb * S_ + n) = make_float2(acc[i][j][2], acc[i][j][3]);
        }
    }
}

// ---------------- generic attention GEMM, occ2 ----------------
__global__ void __launch_bounds__(256, 2) hmma_gemm_k(
    const ushort_t* __restrict__ Ah, int lda,
    const ushort_t* __restrict__ Bh, int ldb,
    float* __restrict__ Cf, ushort_t* __restrict__ Ch,
    int ldc, int K, float alpha,
    const float* __restrict__ biasM, const float* __restrict__ biasN,
    const float* __restrict__ addend, int causal, int kcausal, int mrev) {
    const int by = mrev ? (gridDim.y - 1 - blockIdx.y) : blockIdx.y;
    const int m0 = by * 128, n0 = blockIdx.x * 128;
    if (causal && n0 >= (((m0 >> 10) + 1) << 10)) return;
    int Keff = kcausal ? (((m0 >> 10) + 1) << 10) : K;

    extern __shared__ unsigned char dynsm[];
    const uint32_t sm0 = smem_u32(dynsm);
    const int tid = threadIdx.x, lane = tid & 31, warp = tid >> 5;
    const int wm = warp & 1, wn = warp >> 1;

    HmmaAcc acc;
    #pragma unroll
    for (int i = 0; i < 4; i++)
        #pragma unroll
        for (int j = 0; j < 4; j++)
            #pragma unroll
            for (int r = 0; r < 4; r++) acc.a[i][j][r] = 0.f;

    hmma_mainloop(acc, sm0, tid, Ah, lda, Bh, ldb, m0, n0, Keff >> 5);

    const int mrow = m0 + wm * 64 + (lane >> 2);
    const int ncol = n0 + wn * 32 + (lane & 3) * 2;
    #pragma unroll
    for (int i = 0; i < 4; i++) {
        int ma = mrow + i * 16, mb = ma + 8;
        float bva = biasM ? biasM[ma] : 0.f;
        float bvb = biasM ? biasM[mb] : 0.f;
        #pragma unroll
        for (int j = 0; j < 4; j++) {
            int n = ncol + j * 8;
            float2 va = make_float2(acc.a[i][j][0] * alpha + bva, acc.a[i][j][1] * alpha + bva);
            float2 vb = make_float2(acc.a[i][j][2] * alpha + bvb, acc.a[i][j][3] * alpha + bvb);
            if (biasN) {
                float b0 = biasN[n], b1 = biasN[n + 1];
                va.x += b0; va.y += b1; vb.x += b0; vb.y += b1;
            }
            if (addend) {
                float2 aa = *(const float2*)(addend + (size_t)ma * ldc + n);
                float2 ab = *(const float2*)(addend + (size_t)mb * ldc + n);
                va.x += aa.x; va.y += aa.y; vb.x += ab.x; vb.y += ab.y;
            }
            if (Cf) {
                *(float2*)(Cf + (size_t)ma * ldc + n) = va;
                *(float2*)(Cf + (size_t)mb * ldc + n) = vb;
            }
            if (Ch) {
                *(ushort2*)(Ch + (size_t)ma * ldc + n) = make_ushort2(to_h(va.x), to_h(va.y));
                *(ushort2*)(Ch + (size_t)mb * ldc + n) = make_ushort2(to_h(vb.x), to_h(vb.y));
            }
        }
    }
}

// ---------------- softmax: single gmem pass via smem row buffer ----------------
__global__ void softmax_k() {
    __shared__ float row[S_];
    __shared__ float sh[8];
    int i = blockIdx.x;
    int L = ((i >> 10) + 1) << 10;
    const float4* src = (const float4*)(g_p + ((size_t)i << 13));
    int n4 = L >> 2;
    int tid = threadIdx.x;

    float mx = -1e30f;
    for (int j = tid; j < n4; j += 256) {
        float4 v = src[j];
        *(float4*)(row + 4 * j) = v;
        mx = fmaxf(mx, fmaxf(fmaxf(v.x, v.y), fmaxf(v.z, v.w)));
    }
    float wm = warp_max(mx);
    if ((tid & 31) == 0) sh[tid >> 5] = wm;
    __syncthreads();
    if (tid < 32) {
        float m2 = (tid < 8) ? sh[tid] : -1e30f;
        m2 = warp_max(m2);
        if (tid == 0) sh[0] = m2;
    }
    __syncthreads();
    float m = sh[0];
    __syncthreads();

    float s = 0.f;
    for (int j = tid; j < n4; j += 256) {
        float4 v = *(float4*)(row + 4 * j);
        v.x = __expf(v.x - m); v.y = __expf(v.y - m);
        v.z = __expf(v.z - m); v.w = __expf(v.w - m);
        s += v.x + v.y + v.z + v.w;
        *(float4*)(row + 4 * j) = v;
    }
    float ws = warp_sum(s);
    if ((tid & 31) == 0) sh[tid >> 5] = ws;
    __syncthreads();
    if (tid < 32) {
        float s2 = (tid < 8) ? sh[tid] : 0.f;
        s2 = warp_sum(s2);
        if (tid == 0) sh[0] = s2;
    }
    __syncthreads();
    float inv = 1.f / sh[0];
    size_t base = (size_t)i << 13;
    for (int j = tid; j < n4; j += 256) {
        float4 v = *(float4*)(row + 4 * j);
        uint2 hv = make_uint2(
            (uint32_t)to_h(v.x * inv) | ((uint32_t)to_h(v.y * inv) << 16),
            (uint32_t)to_h(v.z * inv) | ((uint32_t)to_h(v.w * inv) << 16));
        *(uint2*)(g_ph + base + 4 * (size_t)j) = hv;
    }
}

// ---------------- orchestration ----------------
extern "C" void kernel_launch(void* const* d_in, const int* in_sizes, int n_in,
                              void* d_out, int out_size) {
    (void)in_sizes; (void)n_in; (void)out_size;

    float *t1, *y0, *mid, *p;
    ushort_t *wah, *acth, *qh, *kh, *vh, *oh, *ph;
    cudaGetSymbolAddress((void**)&t1,   g_t1);
    cudaGetSymbolAddress((void**)&y0,   g_y0);
    cudaGetSymbolAddress((void**)&mid,  g_mid);
    cudaGetSymbolAddress((void**)&p,    g_p);
    cudaGetSymbolAddress((void**)&wah,  g_wah);
    cudaGetSymbolAddress((void**)&acth, g_ath);
    cudaGetSymbolAddress((void**)&qh,   g_qh);
    cudaGetSymbolAddress((void**)&kh,   g_kh);
    cudaGetSymbolAddress((void**)&vh,   g_vh);
    cudaGetSymbolAddress((void**)&oh,   g_oh);
    cudaGetSymbolAddress((void**)&ph,   g_ph);

    cudaFuncSetAttribute(conv_hmma_k, cudaFuncAttributeMaxDynamicSharedMemorySize, 4 * CSTG);
    cudaFuncSetAttribute(hmma_gemm_k, cudaFuncAttributeMaxDynamicSharedMemorySize, 3 * STG);

    const float* X = (const float*)d_in[0];
    const float* a_gns = (const float*)d_in[17];
    const float* a_gnb = (const float*)d_in[18];
    const float* a_wq  = (const float*)d_in[19];
    const float* a_bq  = (const float*)d_in[20];
    const float* a_wk  = (const float*)d_in[21];
    const float* a_bk  = (const float*)d_in[22];
    const float* a_wv  = (const float*)d_in[23];
    const float* a_bv  = (const float*)d_in[24];
    const float* a_wo  = (const float*)d_in[25];
    const float* a_bo  = (const float*)d_in[26];

    const dim3 conv_grid(16, 32);
    const dim3 nt_grid(S_ / 32, C_ / 32);
    const dim3 nt_blk(32, 8);
    const int WPACK_CONV = ((C_ * KC) / 8) / 256;
    const int WPACK_SQ   = ((C_ * C_) / 8) / 256;

    auto resnet = [&](const float* in, int base, float* midb, float* outbuf,
                      int in_stats_from_part) {
        const float* n1s = (const float*)d_in[base + 0];
        const float* n1b = (const float*)d_in[base + 1];
        const float* w1  = (const float*)d_in[base + 2];
        const float* b1  = (const float*)d_in[base + 3];
        const float* n2s = (const float*)d_in[base + 4];
        const float* n2b = (const float*)d_in[base + 5];
        const float* w2  = (const float*)d_in[base + 6];
        const float* b2  = (const float*)d_in[base + 7];

        if (in_stats_from_part) gn_stats_p<<<NGROUP, 128>>>();
        else                    gn_stats_k<<<NGROUP, 256>>>(in);
        normact_t_k<<<nt_grid, nt_blk>>>(in, n1s, n1b, 1);
        wpack_conv_k<<<WPACK_CONV, 256>>>(w1);
        conv_hmma_k<<<conv_grid, 256, 4 * CSTG>>>();
        ksum_k<<<KSUM_BLOCKS, 256>>>(midb, b1, nullptr);
        gn_stats_p<<<NGROUP, 128>>>();
        normact_t_k<<<nt_grid, nt_blk>>>(midb, n2s, n2b, 1);
        wpack_conv_k<<<WPACK_CONV, 256>>>(w2);
        conv_hmma_k<<<conv_grid, 256, 4 * CSTG>>>();
        ksum_k<<<KSUM_BLOCKS, 256>>>(outbuf, b2, in);
    };

    // ---- ResNet block 0:  X -> y0 ----
    resnet(X, 1, t1, y0, 0);

    // ---- Causal frame attention on y0 (stats via ksum partials) ----
    gn_stats_p<<<NGROUP, 128>>>();
    normact_t_k<<<nt_grid, nt_blk>>>(y0, a_gns, a_gnb, 0);

    // Q[s][d] = act . wq^T + bq
    wpack_k<<<WPACK_SQ, 256>>>(a_wq, wah);
    hmma_gemm_k<<<dim3(4, 64), 256, 3 * STG>>>(acth, C_, wah, C_,
        nullptr, qh, C_, C_, 1.f, nullptr, a_bq, nullptr, 0, 0, 0);
    // K[s][d]
    wpack_k<<<WPACK_SQ, 256>>>(a_wk, wah);
    hmma_gemm_k<<<dim3(4, 64), 256, 3 * STG>>>(acth, C_, wah, C_,
        nullptr, kh, C_, C_, 1.f, nullptr, a_bk, nullptr, 0, 0, 0);
    // V[d][s] = wv . act^T + bv
    wpack_k<<<WPACK_SQ, 256>>>(a_wv, wah);
    hmma_gemm_k<<<dim3(64, 4), 256, 3 * STG>>>(wah, C_, acth, C_,
        nullptr, vh, S_, C_, 1.f, a_bv, nullptr, nullptr, 0, 0, 0);

    // scores: Q . K^T (block-causal tile skip)
    hmma_gemm_k<<<dim3(64, 64), 256, 3 * STG>>>(qh, C_, kh, C_,
        p, nullptr, S_, C_, 0.04419417382415922f,
        nullptr, nullptr, nullptr, 1, 0, 0);
    softmax_k<<<S_, 256>>>();
    // O[s][d] = P . V^T  (reversed m-order, causal K bound)
    hmma_gemm_k<<<dim3(4, 64), 256, 3 * STG>>>(ph, S_, vh, S_,
        nullptr, oh, C_, S_, 1.f, nullptr, nullptr, nullptr, 0, 1, 1);
    // attnout[c][s] = wo . O^T + bo + y0
    wpack_k<<<WPACK_SQ, 256>>>(a_wo, wah);
    hmma_gemm_k<<<dim3(64, 4), 256, 3 * STG>>>(wah, C_, oh, C_,
        t1, nullptr, S_, C_, 1.f, a_bo, nullptr, y0, 0, 0, 0);

    // ---- ResNet block 1:  t1 -> d_out ----
    resnet(t1, 9, mid, (float*)d_out, 0);
}

// round 13
// speedup vs baseline: 1.1245x; 1.1245x over previous
#include <cuda_runtime.h>
#include <cuda_fp16.h>
#include <math.h>
#include <stdint.h>

#define C_      512
#define S_      8192
#define HW_     1024
#define W_      32
#define NGROUP  32
#define CPG     16
#define KC      13824
#define NSPLIT  4
#define KSPLIT_ITERS 108      // (KC/32)/4
#define KSUM_BLOCKS 4096      // (C_*S_/4)/256

// attention smem stage: A 8K | B 8K
#define STG 16384
// conv smem stage: A 8K | B 8K (CTA 128x128, 128 threads)
#define CSTG 16384

typedef unsigned short ushort_t;

__device__ float g_mean[NGROUP];
__device__ float g_rstd[NGROUP];
__device__ float2 g_part[KSUM_BLOCKS];
__device__ float g_t1 [(size_t)C_ * S_];
__device__ float g_y0 [(size_t)C_ * S_];
__device__ float g_mid[(size_t)C_ * S_];
__device__ float g_p  [(size_t)S_ * S_];
__device__ float g_ks [(size_t)NSPLIT * C_ * S_];
// fp16 operands
__device__ __align__(16) ushort_t g_ath[(size_t)S_ * C_];    // normalized act [s][c]
__device__ __align__(16) ushort_t g_wh [(size_t)C_ * KC];    // conv weights, K = r*512+ci
__device__ __align__(16) ushort_t g_wah[(size_t)C_ * C_];
__device__ __align__(16) ushort_t g_qh [(size_t)S_ * C_];
__device__ __align__(16) ushort_t g_kh [(size_t)S_ * C_];
__device__ __align__(16) ushort_t g_vh [(size_t)C_ * S_];
__device__ __align__(16) ushort_t g_oh [(size_t)S_ * C_];
__device__ __align__(16) ushort_t g_ph [(size_t)S_ * S_];

// ---------------- PTX helpers ----------------
__device__ __forceinline__ uint32_t smem_u32(const void* p) {
    uint32_t a;
    asm("{ .reg .u64 t; cvta.to.shared.u64 t, %1; cvt.u32.u64 %0, t; }" : "=r"(a) : "l"(p));
    return a;
}
#define CP_ASYNC16(smem, gmem) \
    asm volatile("cp.async.cg.shared.global [%0], [%1], 16;" :: "r"(smem), "l"(gmem) : "memory")
#define CP_COMMIT() asm volatile("cp.async.commit_group;" ::: "memory")
#define CP_WAIT1()  asm volatile("cp.async.wait_group 1;" ::: "memory")
#define CP_WAIT2()  asm volatile("cp.async.wait_group 2;" ::: "memory")
#define LDSM4(r, addr) \
    asm volatile("ldmatrix.sync.aligned.m8n8.x4.shared.b16 {%0,%1,%2,%3}, [%4];" \
        : "=r"((r)[0]),"=r"((r)[1]),"=r"((r)[2]),"=r"((r)[3]) : "r"(addr))
#define MMA16816(d, a, b0, b1) \
    asm volatile("mma.sync.aligned.m16n8k16.row.col.f32.f16.f16.f32 " \
        "{%0,%1,%2,%3}, {%4,%5,%6,%7}, {%8,%9}, {%0,%1,%2,%3};" \
        : "+f"((d)[0]),"+f"((d)[1]),"+f"((d)[2]),"+f"((d)[3]) \
        : "r"((a)[0]),"r"((a)[1]),"r"((a)[2]),"r"((a)[3]), "r"(b0),"r"(b1))

__device__ __forceinline__ ushort_t to_h(float v) {
    return __half_as_ushort(__float2half_rn(v));
}

__inline__ __device__ float warp_sum(float v) {
    #pragma unroll
    for (int o = 16; o; o >>= 1) v += __shfl_down_sync(0xffffffffu, v, o);
    return v;
}
__inline__ __device__ float warp_max(float v) {
    #pragma unroll
    for (int o = 16; o; o >>= 1) v = fmaxf(v, __shfl_down_sync(0xffffffffu, v, o));
    return v;
}

// ---------------- GroupNorm stats (full read) ----------------
__global__ void gn_stats_k(const float* __restrict__ x) {
    int g = blockIdx.x;
    const float4* p = (const float4*)(x + (size_t)g * CPG * S_);
    const int n4 = (CPG * S_) / 4;
    float s = 0.f, s2 = 0.f;
    for (int i = threadIdx.x; i < n4; i += blockDim.x) {
        float4 v = p[i];
        s  += v.x + v.y + v.z + v.w;
        s2 += v.x * v.x + v.y * v.y + v.z * v.z + v.w * v.w;
    }
    __shared__ float sh0[8], sh1[8];
    float ws = warp_sum(s), ws2 = warp_sum(s2);
    int wid = threadIdx.x >> 5, lid = threadIdx.x & 31;
    if (!lid) { sh0[wid] = ws; sh1[wid] = ws2; }
    __syncthreads();
    if (threadIdx.x == 0) {
        float a = 0.f, b = 0.f;
        #pragma unroll
        for (int i = 0; i < 8; i++) { a += sh0[i]; b += sh1[i]; }
        const float inv_n = 1.f / (float)(CPG * S_);
        float m = a * inv_n;
        g_mean[g] = m;
        g_rstd[g] = rsqrtf(b * inv_n - m * m + 1e-6f);
    }
}

// ---------------- GroupNorm stats from ksum partials ----------------
__global__ void gn_stats_p() {
    int g = blockIdx.x;
    float2 v = g_part[g * 128 + threadIdx.x];
    __shared__ float sh0[4], sh1[4];
    float ws = warp_sum(v.x), ws2 = warp_sum(v.y);
    int wid = threadIdx.x >> 5, lid = threadIdx.x & 31;
    if (!lid) { sh0[wid] = ws; sh1[wid] = ws2; }
    __syncthreads();
    if (threadIdx.x == 0) {
        float a = sh0[0] + sh0[1] + sh0[2] + sh0[3];
        float b = sh1[0] + sh1[1] + sh1[2] + sh1[3];
        const float inv_n = 1.f / (float)(CPG * S_);
        float m = a * inv_n;
        g_mean[g] = m;
        g_rstd[g] = rsqrtf(b * inv_n - m * m + 1e-6f);
    }
}

// ---------------- transposing GN (+optional SiLU): x [c][s] -> fp16 [s][c] ------
__global__ void normact_t_k(const float* __restrict__ x, const float* __restrict__ sc,
                            const float* __restrict__ bi, int do_silu) {
    __shared__ float tile[32][33];
    int s0 = blockIdx.x * 32, c0 = blockIdx.y * 32;
    int tx = threadIdx.x, ty = threadIdx.y;
    #pragma unroll
    for (int i = ty; i < 32; i += 8)
        tile[i][tx] = x[(size_t)(c0 + i) * S_ + s0 + tx];
    __syncthreads();
    int c = c0 + tx;
    int g = c >> 4;
    float mu = g_mean[g], rs = g_rstd[g], sv = sc[c], bv = bi[c];
    #pragma unroll
    for (int i = ty; i < 32; i += 8) {
        float v = (tile[tx][i] - mu) * rs * sv + bv;
        if (do_silu) v = v / (1.f + __expf(-v));
        g_ath[(size_t)(s0 + i) * C_ + c] = to_h(v);
    }
}

// ---------------- conv weight pack: w[co][ci*27+r] -> fp16 g_wh[co][r*512+ci] ----
__global__ void wpack_conv_k(const float* __restrict__ w) {
    size_t id = (size_t)blockIdx.x * 256 + threadIdx.x;
    int co = (int)(id / 1728);
    int kk = (int)(id - (size_t)co * 1728) * 8;
    int r  = kk >> 9;
    int ci0 = kk & 511;
    const float* src = w + (size_t)co * KC + r;
    __align__(16) ushort_t hv[8];
    #pragma unroll
    for (int e = 0; e < 8; e++)
        hv[e] = to_h(src[(size_t)(ci0 + e) * 27]);
    *(uint4*)(g_wh + (size_t)co * KC + kk) = *(uint4*)hv;
}

// ---------------- pack: fp32 row-major -> fp16 (attention weights) ----------------
__global__ void wpack_k(const float* __restrict__ w, ushort_t* __restrict__ dh) {
    size_t id = (size_t)blockIdx.x * 256 + threadIdx.x;
    const float4* src = (const float4*)w;
    float4 v0 = src[id * 2], v1 = src[id * 2 + 1];
    __align__(16) ushort_t hv[8];
    hv[0] = to_h(v0.x); hv[1] = to_h(v0.y); hv[2] = to_h(v0.z); hv[3] = to_h(v0.w);
    hv[4] = to_h(v1.x); hv[5] = to_h(v1.y); hv[6] = to_h(v1.z); hv[7] = to_h(v1.w);
    *(uint4*)(dh + id * 8) = *(uint4*)hv;
}

// ---------------- split-K reduce + per-block GN partials ----------------
__global__ void ksum_k(float* __restrict__ out, const float* __restrict__ bias,
                       const float* __restrict__ addend) {
    size_t i = ((size_t)blockIdx.x * 256 + threadIdx.x) * 4;
    int c = (int)(i >> 13);
    float4 v0 = *(const float4*)(g_ks + i);
    float4 v1 = *(const float4*)(g_ks + (size_t)C_ * S_ + i);
    float4 v2 = *(const float4*)(g_ks + (size_t)2 * C_ * S_ + i);
    float4 v3 = *(const float4*)(g_ks + (size_t)3 * C_ * S_ + i);
    float bv = bias[c];
    float4 r;
    r.x = v0.x + v1.x + v2.x + v3.x + bv;
    r.y = v0.y + v1.y + v2.y + v3.y + bv;
    r.z = v0.z + v1.z + v2.z + v3.z + bv;
    r.w = v0.w + v1.w + v2.w + v3.w + bv;
    if (addend) {
        float4 a = *(const float4*)(addend + i);
        r.x += a.x; r.y += a.y; r.z += a.z; r.w += a.w;
    }
    *(float4*)(out + i) = r;
    float s  = r.x + r.y + r.z + r.w;
    float s2 = r.x * r.x + r.y * r.y + r.z * r.z + r.w * r.w;
    __shared__ float sh0[8], sh1[8];
    float ws = warp_sum(s), ws2 = warp_sum(s2);
    int wid = threadIdx.x >> 5, lid = threadIdx.x & 31;
    if (!lid) { sh0[wid] = ws; sh1[wid] = ws2; }
    __syncthreads();
    if (threadIdx.x == 0) {
        float a = 0.f, b = 0.f;
        #pragma unroll
        for (int k = 0; k < 8; k++) { a += sh0[k]; b += sh1[k]; }
        g_part[blockIdx.x] = make_float2(a, b);
    }
}

// ================= attention HMMA mainloop (3-stage, 1 sync/iter) =================
struct HmmaAcc { float a[4][4][4]; };

__device__ __forceinline__ void hmma_mainloop(
    HmmaAcc& A4, uint32_t sm0, int tid,
    const ushort_t* __restrict__ Ah, int lda,
    const ushort_t* __restrict__ Bh, int ldb,
    int m0, int n0, int kiters) {
    const int lane = tid & 31, warp = tid >> 5;
    const int wm = warp & 1, wn = warp >> 1;

    auto issue = [&](int stage, int k0) {
        uint32_t sb = sm0 + stage * STG;
        #pragma unroll
        for (int h = 0; h < 2; h++) {
            int id = tid + h * 256;
            int r = id >> 2, cu = id & 3;
            uint32_t soff = r * 64 + (((cu ^ ((r >> 1) & 3))) << 4);
            CP_ASYNC16(sb + soff,        Ah + (size_t)(m0 + r) * lda + k0 + cu * 8);
            CP_ASYNC16(sb + 8192 + soff, Bh + (size_t)(n0 + r) * ldb + k0 + cu * 8);
        }
        CP_COMMIT();
    };

    issue(0, 0);
    issue(1, 32);

    const int rl = lane & 15, ul = lane >> 4;
    for (int it = 0; it < kiters; it++) {
        CP_WAIT1();
        __syncthreads();
        if (it + 2 < kiters) issue((it + 2) % 3, (it + 2) * 32);
        else CP_COMMIT();
        uint32_t sb = sm0 + (it % 3) * STG;
        #pragma unroll
        for (int k16 = 0; k16 < 2; k16++) {
            uint32_t a4[4][4], b4[2][4];
            int u = k16 * 2 + ul;
            #pragma unroll
            for (int i = 0; i < 4; i++) {
                int r = wm * 64 + i * 16 + rl;
                LDSM4(a4[i], sb + r * 64 + (((u ^ ((r >> 1) & 3))) << 4));
            }
            #pragma unroll
            for (int j2 = 0; j2 < 2; j2++) {
                int r = wn * 32 + j2 * 16 + rl;
                LDSM4(b4[j2], sb + 8192 + r * 64 + (((u ^ ((r >> 1) & 3))) << 4));
            }
            #pragma unroll
            for (int i = 0; i < 4; i++)
                #pragma unroll
                for (int j = 0; j < 4; j++) {
                    int j2 = j >> 1, ts = j & 1;
                    MMA16816(A4.a[i][j], a4[i], b4[j2][ts], b4[j2][ts + 2]);
                }
        }
    }
}

// ---------------- conv GEMM: CTA 128x128, 4 warps of 64x64, occ2, implicit gather --
// grid (16, 64): x -> m-tile (x&3), ksplit (x>>2); y -> n-tile. 128 threads.
__global__ void __launch_bounds__(128, 2) conv_hmma_k() {
    extern __shared__ unsigned char dynsm[];
    const uint32_t sm0 = smem_u32(dynsm);
    const int tid = threadIdx.x, lane = tid & 31, warp = tid >> 5;
    const int m0 = (blockIdx.x & 3) * 128;
    const int ks = blockIdx.x >> 2;
    const int n0 = blockIdx.y * 128;
    const int kbase = ks * (KSPLIT_ITERS * 32);
    const int wm = warp & 1, wn = warp >> 1;   // warp tile: m 64, n 64

    // loaders: A 512 chunks, B 512 chunks; 128 threads -> 4 each
    int row4[4], cu8[4];
    uint32_t soff4[4];
    int tm2[4], ym1[4], xm1[4];
    #pragma unroll
    for (int h = 0; h < 4; h++) {
        int id = tid + h * 128;
        int r = id >> 2, cu = id & 3;
        row4[h] = r; cu8[h] = cu * 8;
        soff4[h] = r * 64 + (((cu ^ ((r >> 1) & 3))) << 4);
        int pos = n0 + r;
        tm2[h] = (pos >> 10) - 2;
        ym1[h] = ((pos >> 5) & 31) - 1;
        xm1[h] = (pos & 31) - 1;
    }

    auto issue = [&](int stage, int k0) {
        uint32_t sb = sm0 + stage * CSTG;
        int rcode = k0 >> 9;
        int ci0 = k0 & 511;
        int kd = rcode / 9;
        int rr = rcode - kd * 9;
        int kh = rr / 3;
        int kw = rr - kh * 3;
        #pragma unroll
        for (int h = 0; h < 4; h++) {
            CP_ASYNC16(sb + soff4[h],
                       g_wh + (size_t)(m0 + row4[h]) * KC + k0 + cu8[h]);
            int ts = min(max(tm2[h] + kd, 0), 7);
            int ys = min(max(ym1[h] + kh, 0), 31);
            int xs = min(max(xm1[h] + kw, 0), 31);
            CP_ASYNC16(sb + 8192 + soff4[h],
                       g_ath + (size_t)((ts << 10) + (ys << 5) + xs) * C_ + ci0 + cu8[h]);
        }
        CP_COMMIT();
    };

    float acc[4][8][4];
    #pragma unroll
    for (int i = 0; i < 4; i++)
        #pragma unroll
        for (int j = 0; j < 8; j++)
            #pragma unroll
            for (int r = 0; r < 4; r++) acc[i][j][r] = 0.f;

    issue(0, kbase);
    issue(1, kbase + 32);
    issue(2, kbase + 64);

    const int rl = lane & 15, ul = lane >> 4;
    for (int it = 0; it < KSPLIT_ITERS; it++) {
        CP_WAIT2();
        __syncthreads();
        if (it + 3 < KSPLIT_ITERS) issue((it + 3) & 3, kbase + (it + 3) * 32);
        else CP_COMMIT();
        uint32_t sb = sm0 + (it & 3) * CSTG;
        #pragma unroll
        for (int k16 = 0; k16 < 2; k16++) {
            uint32_t a4[4][4], b4[4][4];
            int u = k16 * 2 + ul;
            #pragma unroll
            for (int i = 0; i < 4; i++) {
                int r = wm * 64 + i * 16 + rl;
                LDSM4(a4[i], sb + r * 64 + (((u ^ ((r >> 1) & 3))) << 4));
            }
            #pragma unroll
            for (int j2 = 0; j2 < 4; j2++) {
                int r = wn * 64 + j2 * 16 + rl;
                LDSM4(b4[j2], sb + 8192 + r * 64 + (((u ^ ((r >> 1) & 3))) << 4));
            }
            #pragma unroll
            for (int i = 0; i < 4; i++)
                #pragma unroll
                for (int j = 0; j < 8; j++) {
                    int j2 = j >> 1, ts = j & 1;
                    MMA16816(acc[i][j], a4[i], b4[j2][ts], b4[j2][ts + 2]);
                }
        }
    }

    float* Sp = g_ks + (size_t)ks * C_ * S_;
    const int mrow = m0 + wm * 64 + (lane >> 2);
    const int ncol = n0 + wn * 64 + (lane & 3) * 2;
    #pragma unroll
    for (int i = 0; i < 4; i++) {
        int ma = mrow + i * 16, mb = ma + 8;
        #pragma unroll
        for (int j = 0; j < 8; j++) {
            int n = ncol + j * 8;
            *(float2*)(Sp + (size_t)ma * S_ + n) = make_float2(acc[i][j][0], acc[i][j][1]);
            *(float2*)(Sp + (size_t)mb * S_ + n) = make_float2(acc[i][j][2], acc[i][j][3]);
        }
    }
}

// ---------------- generic attention GEMM, occ2 ----------------
__global__ void __launch_bounds__(256, 2) hmma_gemm_k(
    const ushort_t* __restrict__ Ah, int lda,
    const ushort_t* __restrict__ Bh, int ldb,
    float* __restrict__ Cf, ushort_t* __restrict__ Ch,
    int ldc, int K, float alpha,
    const float* __restrict__ biasM, const float* __restrict__ biasN,
    const float* __restrict__ addend, int causal, int kcausal, int mrev) {
    const int by = mrev ? (gridDim.y - 1 - blockIdx.y) : blockIdx.y;
    const int m0 = by * 128, n0 = blockIdx.x * 128;
    if (causal && n0 >= (((m0 >> 10) + 1) << 10)) return;
    int Keff = kcausal ? (((m0 >> 10) + 1) << 10) : K;

    extern __shared__ unsigned char dynsm[];
    const uint32_t sm0 = smem_u32(dynsm);
    const int tid = threadIdx.x, lane = tid & 31, warp = tid >> 5;
    const int wm = warp & 1, wn = warp >> 1;

    HmmaAcc acc;
    #pragma unroll
    for (int i = 0; i < 4; i++)
        #pragma unroll
        for (int j = 0; j < 4; j++)
            #pragma unroll
            for (int r = 0; r < 4; r++) acc.a[i][j][r] = 0.f;

    hmma_mainloop(acc, sm0, tid, Ah, lda, Bh, ldb, m0, n0, Keff >> 5);

    const int mrow = m0 + wm * 64 + (lane >> 2);
    const int ncol = n0 + wn * 32 + (lane & 3) * 2;
    #pragma unroll
    for (int i = 0; i < 4; i++) {
        int ma = mrow + i * 16, mb = ma + 8;
        float bva = biasM ? biasM[ma] : 0.f;
        float bvb = biasM ? biasM[mb] : 0.f;
        #pragma unroll
        for (int j = 0; j < 4; j++) {
            int n = ncol + j * 8;
            float2 va = make_float2(acc.a[i][j][0] * alpha + bva, acc.a[i][j][1] * alpha + bva);
            float2 vb = make_float2(acc.a[i][j][2] * alpha + bvb, acc.a[i][j][3] * alpha + bvb);
            if (biasN) {
                float b0 = biasN[n], b1 = biasN[n + 1];
                va.x += b0; va.y += b1; vb.x += b0; vb.y += b1;
            }
            if (addend) {
                float2 aa = *(const float2*)(addend + (size_t)ma * ldc + n);
                float2 ab = *(const float2*)(addend + (size_t)mb * ldc + n);
                va.x += aa.x; va.y += aa.y; vb.x += ab.x; vb.y += ab.y;
            }
            if (Cf) {
                *(float2*)(Cf + (size_t)ma * ldc + n) = va;
                *(float2*)(Cf + (size_t)mb * ldc + n) = vb;
            }
            if (Ch) {
                *(ushort2*)(Ch + (size_t)ma * ldc + n) = make_ushort2(to_h(va.x), to_h(va.y));
                *(ushort2*)(Ch + (size_t)mb * ldc + n) = make_ushort2(to_h(vb.x), to_h(vb.y));
            }
        }
    }
}

// ---------------- softmax: single gmem pass via smem row buffer ----------------
__global__ void softmax_k() {
    __shared__ float row[S_];
    __shared__ float sh[8];
    int i = blockIdx.x;
    int L = ((i >> 10) + 1) << 10;
    const float4* src = (const float4*)(g_p + ((size_t)i << 13));
    int n4 = L >> 2;
    int tid = threadIdx.x;

    float mx = -1e30f;
    for (int j = tid; j < n4; j += 256) {
        float4 v = src[j];
        *(float4*)(row + 4 * j) = v;
        mx = fmaxf(mx, fmaxf(fmaxf(v.x, v.y), fmaxf(v.z, v.w)));
    }
    float wm = warp_max(mx);
    if ((tid & 31) == 0) sh[tid >> 5] = wm;
    __syncthreads();
    if (tid < 32) {
        float m2 = (tid < 8) ? sh[tid] : -1e30f;
        m2 = warp_max(m2);
        if (tid == 0) sh[0] = m2;
    }
    __syncthreads();
    float m = sh[0];
    __syncthreads();

    float s = 0.f;
    for (int j = tid; j < n4; j += 256) {
        float4 v = *(float4*)(row + 4 * j);
        v.x = __expf(v.x - m); v.y = __expf(v.y - m);
        v.z = __expf(v.z - m); v.w = __expf(v.w - m);
        s += v.x + v.y + v.z + v.w;
        *(float4*)(row + 4 * j) = v;
    }
    float ws = warp_sum(s);
    if ((tid & 31) == 0) sh[tid >> 5] = ws;
    __syncthreads();
    if (tid < 32) {
        float s2 = (tid < 8) ? sh[tid] : 0.f;
        s2 = warp_sum(s2);
        if (tid == 0) sh[0] = s2;
    }
    __syncthreads();
    float inv = 1.f / sh[0];
    size_t base = (size_t)i << 13;
    for (int j = tid; j < n4; j += 256) {
        float4 v = *(float4*)(row + 4 * j);
        uint2 hv = make_uint2(
            (uint32_t)to_h(v.x * inv) | ((uint32_t)to_h(v.y * inv) << 16),
            (uint32_t)to_h(v.z * inv) | ((uint32_t)to_h(v.w * inv) << 16));
        *(uint2*)(g_ph + base + 4 * (size_t)j) = hv;
    }
}

// ---------------- orchestration ----------------
extern "C" void kernel_launch(void* const* d_in, const int* in_sizes, int n_in,
                              void* d_out, int out_size) {
    (void)in_sizes; (void)n_in; (void)out_size;

    float *t1, *y0, *mid, *p;
    ushort_t *wah, *acth, *qh, *kh, *vh, *oh, *ph;
    cudaGetSymbolAddress((void**)&t1,   g_t1);
    cudaGetSymbolAddress((void**)&y0,   g_y0);
    cudaGetSymbolAddress((void**)&mid,  g_mid);
    cudaGetSymbolAddress((void**)&p,    g_p);
    cudaGetSymbolAddress((void**)&wah,  g_wah);
    cudaGetSymbolAddress((void**)&acth, g_ath);
    cudaGetSymbolAddress((void**)&qh,   g_qh);
    cudaGetSymbolAddress((void**)&kh,   g_kh);
    cudaGetSymbolAddress((void**)&vh,   g_vh);
    cudaGetSymbolAddress((void**)&oh,   g_oh);
    cudaGetSymbolAddress((void**)&ph,   g_ph);

    cudaFuncSetAttribute(conv_hmma_k, cudaFuncAttributeMaxDynamicSharedMemorySize, 4 * CSTG);
    cudaFuncSetAttribute(hmma_gemm_k, cudaFuncAttributeMaxDynamicSharedMemorySize, 3 * STG);

    const float* X = (const float*)d_in[0];
    const float* a_gns = (const float*)d_in[17];
    const float* a_gnb = (const float*)d_in[18];
    const float* a_wq  = (const float*)d_in[19];
    const float* a_bq  = (const float*)d_in[20];
    const float* a_wk  = (const float*)d_in[21];
    const float* a_bk  = (const float*)d_in[22];
    const float* a_wv  = (const float*)d_in[23];
    const float* a_bv  = (const float*)d_in[24];
    const float* a_wo  = (const float*)d_in[25];
    const float* a_bo  = (const float*)d_in[26];

    const dim3 conv_grid(16, 64);
    const dim3 nt_grid(S_ / 32, C_ / 32);
    const dim3 nt_blk(32, 8);
    const int WPACK_CONV = ((C_ * KC) / 8) / 256;
    const int WPACK_SQ   = ((C_ * C_) / 8) / 256;

    auto resnet = [&](const float* in, int base, float* midb, float* outbuf,
                      int in_stats_from_part) {
        const float* n1s = (const float*)d_in[base + 0];
        const float* n1b = (const float*)d_in[base + 1];
        const float* w1  = (const float*)d_in[base + 2];
        const float* b1  = (const float*)d_in[base + 3];
        const float* n2s = (const float*)d_in[base + 4];
        const float* n2b = (const float*)d_in[base + 5];
        const float* w2  = (const float*)d_in[base + 6];
        const float* b2  = (const float*)d_in[base + 7];

        if (in_stats_from_part) gn_stats_p<<<NGROUP, 128>>>();
        else                    gn_stats_k<<<NGROUP, 256>>>(in);
        normact_t_k<<<nt_grid, nt_blk>>>(in, n1s, n1b, 1);
        wpack_conv_k<<<WPACK_CONV, 256>>>(w1);
        conv_hmma_k<<<conv_grid, 128, 4 * CSTG>>>();
        ksum_k<<<KSUM_BLOCKS, 256>>>(midb, b1, nullptr);
        gn_stats_p<<<NGROUP, 128>>>();
        normact_t_k<<<nt_grid, nt_blk>>>(midb, n2s, n2b, 1);
        wpack_conv_k<<<WPACK_CONV, 256>>>(w2);
        conv_hmma_k<<<conv_grid, 128, 4 * CSTG>>>();
        ksum_k<<<KSUM_BLOCKS, 256>>>(outbuf, b2, in);
    };

    // ---- ResNet block 0:  X -> y0 ----
    resnet(X, 1, t1, y0, 0);

    // ---- Causal frame attention on y0 (stats via ksum partials) ----
    gn_stats_p<<<NGROUP, 128>>>();
    normact_t_k<<<nt_grid, nt_blk>>>(y0, a_gns, a_gnb, 0);

    // Q[s][d] = act . wq^T + bq
    wpack_k<<<WPACK_SQ, 256>>>(a_wq, wah);
    hmma_gemm_k<<<dim3(4, 64), 256, 3 * STG>>>(acth, C_, wah, C_,
        nullptr, qh, C_, C_, 1.f, nullptr, a_bq, nullptr, 0, 0, 0);
    // K[s][d]
    wpack_k<<<WPACK_SQ, 256>>>(a_wk, wah);
    hmma_gemm_k<<<dim3(4, 64), 256, 3 * STG>>>(acth, C_, wah, C_,
        nullptr, kh, C_, C_, 1.f, nullptr, a_bk, nullptr, 0, 0, 0);
    // V[d][s] = wv . act^T + bv
    wpack_k<<<WPACK_SQ, 256>>>(a_wv, wah);
    hmma_gemm_k<<<dim3(64, 4), 256, 3 * STG>>>(wah, C_, acth, C_,
        nullptr, vh, S_, C_, 1.f, a_bv, nullptr, nullptr, 0, 0, 0);

    // scores: Q . K^T (block-causal tile skip)
    hmma_gemm_k<<<dim3(64, 64), 256, 3 * STG>>>(qh, C_, kh, C_,
        p, nullptr, S_, C_, 0.04419417382415922f,
        nullptr, nullptr, nullptr, 1, 0, 0);
    softmax_k<<<S_, 256>>>();
    // O[s][d] = P . V^T  (reversed m-order, causal K bound)
    hmma_gemm_k<<<dim3(4, 64), 256, 3 * STG>>>(ph, S_, vh, S_,
        nullptr, oh, C_, S_, 1.f, nullptr, nullptr, nullptr, 0, 1, 1);
    // attnout[c][s] = wo . O^T + bo + y0
    wpack_k<<<WPACK_SQ, 256>>>(a_wo, wah);
    hmma_gemm_k<<<dim3(64, 4), 256, 3 * STG>>>(wah, C_, oh, C_,
        t1, nullptr, S_, C_, 1.f, a_bo, nullptr, y0, 0, 0, 0);

    // ---- ResNet block 1:  t1 -> d_out ----
    resnet(t1, 9, mid, (float*)d_out, 0);
}

// round 14
// speedup vs baseline: 1.1297x; 1.0046x over previous
#include <cuda_runtime.h>
#include <cuda_fp16.h>
#include <math.h>
#include <stdint.h>

#define C_      512
#define S_      8192
#define HW_     1024
#define W_      32
#define NGROUP  32
#define CPG     16
#define KC      13824
#define NSPLIT  4
#define KSPLIT_ITERS 108      // (KC/32)/4
#define KSUM_BLOCKS 4096      // (C_*S_/4)/256

#define STG 16384             // GEMM smem stage: A 8K | B 8K

typedef unsigned short ushort_t;

__device__ float g_mean[NGROUP];
__device__ float g_rstd[NGROUP];
__device__ float2 g_part[KSUM_BLOCKS];
__device__ float g_t1 [(size_t)C_ * S_];
__device__ float g_y0 [(size_t)C_ * S_];
__device__ float g_mid[(size_t)C_ * S_];
__device__ float g_p  [(size_t)S_ * S_];
__device__ float g_ks [(size_t)NSPLIT * C_ * S_];
__device__ __align__(16) ushort_t g_ath[(size_t)S_ * C_];    // normalized act [s][c]
__device__ __align__(16) ushort_t g_wh [(size_t)C_ * KC];    // conv weights, K = r*512+ci
__device__ __align__(16) ushort_t g_wah[(size_t)C_ * C_];
__device__ __align__(16) ushort_t g_qh [(size_t)S_ * C_];
__device__ __align__(16) ushort_t g_kh [(size_t)S_ * C_];
__device__ __align__(16) ushort_t g_vh [(size_t)C_ * S_];
__device__ __align__(16) ushort_t g_oh [(size_t)S_ * C_];
__device__ __align__(16) ushort_t g_ph [(size_t)S_ * S_];

// ---------------- PTX helpers ----------------
__device__ __forceinline__ uint32_t smem_u32(const void* p) {
    uint32_t a;
    asm("{ .reg .u64 t; cvta.to.shared.u64 t, %1; cvt.u32.u64 %0, t; }" : "=r"(a) : "l"(p));
    return a;
}
#define CP_ASYNC16(smem, gmem) \
    asm volatile("cp.async.cg.shared.global [%0], [%1], 16;" :: "r"(smem), "l"(gmem) : "memory")
#define CP_COMMIT() asm volatile("cp.async.commit_group;" ::: "memory")
#define CP_WAIT1()  asm volatile("cp.async.wait_group 1;" ::: "memory")
#define CP_WAIT2()  asm volatile("cp.async.wait_group 2;" ::: "memory")
#define LDSM4(r, addr) \
    asm volatile("ldmatrix.sync.aligned.m8n8.x4.shared.b16 {%0,%1,%2,%3}, [%4];" \
        : "=r"((r)[0]),"=r"((r)[1]),"=r"((r)[2]),"=r"((r)[3]) : "r"(addr))
#define MMA16816(d, a, b0, b1) \
    asm volatile("mma.sync.aligned.m16n8k16.row.col.f32.f16.f16.f32 " \
        "{%0,%1,%2,%3}, {%4,%5,%6,%7}, {%8,%9}, {%0,%1,%2,%3};" \
        : "+f"((d)[0]),"+f"((d)[1]),"+f"((d)[2]),"+f"((d)[3]) \
        : "r"((a)[0]),"r"((a)[1]),"r"((a)[2]),"r"((a)[3]), "r"(b0),"r"(b1))

__device__ __forceinline__ ushort_t to_h(float v) {
    return __half_as_ushort(__float2half_rn(v));
}

__inline__ __device__ float warp_sum(float v) {
    #pragma unroll
    for (int o = 16; o; o >>= 1) v += __shfl_down_sync(0xffffffffu, v, o);
    return v;
}
__inline__ __device__ float warp_max(float v) {
    #pragma unroll
    for (int o = 16; o; o >>= 1) v = fmaxf(v, __shfl_down_sync(0xffffffffu, v, o));
    return v;
}

// ---------------- GroupNorm stats (full read) ----------------
__global__ void gn_stats_k(const float* __restrict__ x) {
    int g = blockIdx.x;
    const float4* p = (const float4*)(x + (size_t)g * CPG * S_);
    const int n4 = (CPG * S_) / 4;
    float s = 0.f, s2 = 0.f;
    for (int i = threadIdx.x; i < n4; i += blockDim.x) {
        float4 v = p[i];
        s  += v.x + v.y + v.z + v.w;
        s2 += v.x * v.x + v.y * v.y + v.z * v.z + v.w * v.w;
    }
    __shared__ float sh0[8], sh1[8];
    float ws = warp_sum(s), ws2 = warp_sum(s2);
    int wid = threadIdx.x >> 5, lid = threadIdx.x & 31;
    if (!lid) { sh0[wid] = ws; sh1[wid] = ws2; }
    __syncthreads();
    if (threadIdx.x == 0) {
        float a = 0.f, b = 0.f;
        #pragma unroll
        for (int i = 0; i < 8; i++) { a += sh0[i]; b += sh1[i]; }
        const float inv_n = 1.f / (float)(CPG * S_);
        float m = a * inv_n;
        g_mean[g] = m;
        g_rstd[g] = rsqrtf(b * inv_n - m * m + 1e-6f);
    }
}

// ---------------- GroupNorm stats from ksum partials ----------------
__global__ void gn_stats_p() {
    int g = blockIdx.x;
    float2 v = g_part[g * 128 + threadIdx.x];
    __shared__ float sh0[4], sh1[4];
    float ws = warp_sum(v.x), ws2 = warp_sum(v.y);
    int wid = threadIdx.x >> 5, lid = threadIdx.x & 31;
    if (!lid) { sh0[wid] = ws; sh1[wid] = ws2; }
    __syncthreads();
    if (threadIdx.x == 0) {
        float a = sh0[0] + sh0[1] + sh0[2] + sh0[3];
        float b = sh1[0] + sh1[1] + sh1[2] + sh1[3];
        const float inv_n = 1.f / (float)(CPG * S_);
        float m = a * inv_n;
        g_mean[g] = m;
        g_rstd[g] = rsqrtf(b * inv_n - m * m + 1e-6f);
    }
}

// ---------------- transposing GN (+optional SiLU): x [c][s] -> fp16 [s][c] ------
__global__ void normact_t_k(const float* __restrict__ x, const float* __restrict__ sc,
                            const float* __restrict__ bi, int do_silu) {
    __shared__ float tile[32][33];
    int s0 = blockIdx.x * 32, c0 = blockIdx.y * 32;
    int tx = threadIdx.x, ty = threadIdx.y;
    #pragma unroll
    for (int i = ty; i < 32; i += 8)
        tile[i][tx] = x[(size_t)(c0 + i) * S_ + s0 + tx];
    __syncthreads();
    int c = c0 + tx;
    int g = c >> 4;
    float mu = g_mean[g], rs = g_rstd[g], sv = sc[c], bv = bi[c];
    #pragma unroll
    for (int i = ty; i < 32; i += 8) {
        float v = (tile[tx][i] - mu) * rs * sv + bv;
        if (do_silu) v = v / (1.f + __expf(-v));
        g_ath[(size_t)(s0 + i) * C_ + c] = to_h(v);
    }
}

// ---------------- conv weight pack (smem transpose, contiguous reads) ----------
// one block per co: load w[co][0..13823] contiguously, emit g_wh[co][r*512+ci]
__global__ void wpack_conv_k(const float* __restrict__ w) {
    extern __shared__ float buf[];
    int co = blockIdx.x;
    const float4* src = (const float4*)(w + (size_t)co * KC);
    for (int i = threadIdx.x; i < KC / 4; i += 256)
        *(float4*)&buf[i * 4] = src[i];
    __syncthreads();
    for (int i = threadIdx.x; i < KC / 8; i += 256) {
        int kk = i * 8;
        int r = kk >> 9, ci0 = kk & 511;
        __align__(16) ushort_t hv[8];
        #pragma unroll
        for (int e = 0; e < 8; e++)
            hv[e] = to_h(buf[(ci0 + e) * 27 + r]);
        *(uint4*)(g_wh + (size_t)co * KC + kk) = *(uint4*)hv;
    }
}

// ---------------- pack: fp32 row-major -> fp16 (attention weights) ----------------
__global__ void wpack_k(const float* __restrict__ w, ushort_t* __restrict__ dh) {
    size_t id = (size_t)blockIdx.x * 256 + threadIdx.x;
    const float4* src = (const float4*)w;
    float4 v0 = src[id * 2], v1 = src[id * 2 + 1];
    __align__(16) ushort_t hv[8];
    hv[0] = to_h(v0.x); hv[1] = to_h(v0.y); hv[2] = to_h(v0.z); hv[3] = to_h(v0.w);
    hv[4] = to_h(v1.x); hv[5] = to_h(v1.y); hv[6] = to_h(v1.z); hv[7] = to_h(v1.w);
    *(uint4*)(dh + id * 8) = *(uint4*)hv;
}

// ---------------- split-K reduce + per-block GN partials ----------------
__global__ void ksum_k(float* __restrict__ out, const float* __restrict__ bias,
                       const float* __restrict__ addend) {
    size_t i = ((size_t)blockIdx.x * 256 + threadIdx.x) * 4;
    int c = (int)(i >> 13);
    float4 v0 = *(const float4*)(g_ks + i);
    float4 v1 = *(const float4*)(g_ks + (size_t)C_ * S_ + i);
    float4 v2 = *(const float4*)(g_ks + (size_t)2 * C_ * S_ + i);
    float4 v3 = *(const float4*)(g_ks + (size_t)3 * C_ * S_ + i);
    float bv = bias[c];
    float4 r;
    r.x = v0.x + v1.x + v2.x + v3.x + bv;
    r.y = v0.y + v1.y + v2.y + v3.y + bv;
    r.z = v0.z + v1.z + v2.z + v3.z + bv;
    r.w = v0.w + v1.w + v2.w + v3.w + bv;
    if (addend) {
        float4 a = *(const float4*)(addend + i);
        r.x += a.x; r.y += a.y; r.z += a.z; r.w += a.w;
    }
    *(float4*)(out + i) = r;
    float s  = r.x + r.y + r.z + r.w;
    float s2 = r.x * r.x + r.y * r.y + r.z * r.z + r.w * r.w;
    __shared__ float sh0[8], sh1[8];
    float ws = warp_sum(s), ws2 = warp_sum(s2);
    int wid = threadIdx.x >> 5, lid = threadIdx.x & 31;
    if (!lid) { sh0[wid] = ws; sh1[wid] = ws2; }
    __syncthreads();
    if (threadIdx.x == 0) {
        float a = 0.f, b = 0.f;
        #pragma unroll
        for (int k = 0; k < 8; k++) { a += sh0[k]; b += sh1[k]; }
        g_part[blockIdx.x] = make_float2(a, b);
    }
}

// ================= attention HMMA mainloop (3-stage, 1 sync/iter) =================
struct HmmaAcc { float a[4][4][4]; };

__device__ __forceinline__ void hmma_mainloop(
    HmmaAcc& A4, uint32_t sm0, int tid,
    const ushort_t* __restrict__ Ah, int lda,
    const ushort_t* __restrict__ Bh, int ldb,
    int m0, int n0, int kiters) {
    const int lane = tid & 31, warp = tid >> 5;
    const int wm = warp & 1, wn = warp >> 1;

    auto issue = [&](int stage, int k0) {
        uint32_t sb = sm0 + stage * STG;
        #pragma unroll
        for (int h = 0; h < 2; h++) {
            int id = tid + h * 256;
            int r = id >> 2, cu = id & 3;
            uint32_t soff = r * 64 + (((cu ^ ((r >> 1) & 3))) << 4);
            CP_ASYNC16(sb + soff,        Ah + (size_t)(m0 + r) * lda + k0 + cu * 8);
            CP_ASYNC16(sb + 8192 + soff, Bh + (size_t)(n0 + r) * ldb + k0 + cu * 8);
        }
        CP_COMMIT();
    };

    issue(0, 0);
    issue(1, 32);

    const int rl = lane & 15, ul = lane >> 4;
    for (int it = 0; it < kiters; it++) {
        CP_WAIT1();
        __syncthreads();
        if (it + 2 < kiters) issue((it + 2) % 3, (it + 2) * 32);
        else CP_COMMIT();
        uint32_t sb = sm0 + (it % 3) * STG;
        #pragma unroll
        for (int k16 = 0; k16 < 2; k16++) {
            uint32_t a4[4][4], b4[2][4];
            int u = k16 * 2 + ul;
            #pragma unroll
            for (int i = 0; i < 4; i++) {
                int r = wm * 64 + i * 16 + rl;
                LDSM4(a4[i], sb + r * 64 + (((u ^ ((r >> 1) & 3))) << 4));
            }
            #pragma unroll
            for (int j2 = 0; j2 < 2; j2++) {
                int r = wn * 32 + j2 * 16 + rl;
                LDSM4(b4[j2], sb + 8192 + r * 64 + (((u ^ ((r >> 1) & 3))) << 4));
            }
            #pragma unroll
            for (int i = 0; i < 4; i++)
                #pragma unroll
                for (int j = 0; j < 4; j++) {
                    int j2 = j >> 1, ts = j & 1;
                    MMA16816(A4.a[i][j], a4[i], b4[j2][ts], b4[j2][ts + 2]);
                }
        }
    }
}

// ---------------- conv GEMM (R11 config): implicit gather, split-K, 4-stage, occ2 --
// grid (16, 64): x -> m-tile (x&3), ksplit (x>>2); y -> n-tile. 256 threads.
__global__ void __launch_bounds__(256, 2) conv_hmma_k() {
    extern __shared__ unsigned char dynsm[];
    const uint32_t sm0 = smem_u32(dynsm);
    const int tid = threadIdx.x, lane = tid & 31, warp = tid >> 5;
    const int m0 = (blockIdx.x & 3) * 128;
    const int ks = blockIdx.x >> 2;
    const int n0 = blockIdx.y * 128;
    const int kbase = ks * (KSPLIT_ITERS * 32);
    const int wm = warp & 1, wn = warp >> 1;

    int rrow[2], cu8[2];
    uint32_t soffv[2];
    int tm2[2], ym1[2], xm1[2];
    #pragma unroll
    for (int h = 0; h < 2; h++) {
        int id = tid + h * 256;
        int r = id >> 2, cu = id & 3;
        rrow[h] = r; cu8[h] = cu * 8;
        soffv[h] = r * 64 + (((cu ^ ((r >> 1) & 3))) << 4);
        int pos = n0 + r;
        tm2[h] = (pos >> 10) - 2;
        ym1[h] = ((pos >> 5) & 31) - 1;
        xm1[h] = (pos & 31) - 1;
    }

    auto issue = [&](int stage, int k0) {
        uint32_t sb = sm0 + stage * STG;
        int rcode = k0 >> 9;
        int ci0 = k0 & 511;
        int kd = rcode / 9;
        int rr = rcode - kd * 9;
        int kh = rr / 3;
        int kw = rr - kh * 3;
        #pragma unroll
        for (int h = 0; h < 2; h++) {
            CP_ASYNC16(sb + soffv[h],
                       g_wh + (size_t)(m0 + rrow[h]) * KC + k0 + cu8[h]);
            int ts = min(max(tm2[h] + kd, 0), 7);
            int ys = min(max(ym1[h] + kh, 0), 31);
            int xs = min(max(xm1[h] + kw, 0), 31);
            CP_ASYNC16(sb + 8192 + soffv[h],
                       g_ath + (size_t)((ts << 10) + (ys << 5) + xs) * C_ + ci0 + cu8[h]);
        }
        CP_COMMIT();
    };

    float acc[4][4][4];
    #pragma unroll
    for (int i = 0; i < 4; i++)
        #pragma unroll
        for (int j = 0; j < 4; j++)
            #pragma unroll
            for (int r = 0; r < 4; r++) acc[i][j][r] = 0.f;

    issue(0, kbase);
    issue(1, kbase + 32);
    issue(2, kbase + 64);

    const int rl = lane & 15, ul = lane >> 4;
    for (int it = 0; it < KSPLIT_ITERS; it++) {
        CP_WAIT2();
        __syncthreads();
        if (it + 3 < KSPLIT_ITERS) issue((it + 3) & 3, kbase + (it + 3) * 32);
        else CP_COMMIT();
        uint32_t sb = sm0 + (it & 3) * STG;
        #pragma unroll
        for (int k16 = 0; k16 < 2; k16++) {
            uint32_t a4[4][4], b4[2][4];
            int u = k16 * 2 + ul;
            #pragma unroll
            for (int i = 0; i < 4; i++) {
                int r = wm * 64 + i * 16 + rl;
                LDSM4(a4[i], sb + r * 64 + (((u ^ ((r >> 1) & 3))) << 4));
            }
            #pragma unroll
            for (int j2 = 0; j2 < 2; j2++) {
                int r = wn * 32 + j2 * 16 + rl;
                LDSM4(b4[j2], sb + 8192 + r * 64 + (((u ^ ((r >> 1) & 3))) << 4));
            }
            #pragma unroll
            for (int i = 0; i < 4; i++)
                #pragma unroll
                for (int j = 0; j < 4; j++) {
                    int j2 = j >> 1, ts = j & 1;
                    MMA16816(acc[i][j], a4[i], b4[j2][ts], b4[j2][ts + 2]);
                }
        }
    }

    float* Sp = g_ks + (size_t)ks * C_ * S_;
    const int mrow = m0 + wm * 64 + (lane >> 2);
    const int ncol = n0 + wn * 32 + (lane & 3) * 2;
    #pragma unroll
    for (int i = 0; i < 4; i++) {
        int ma = mrow + i * 16, mb = ma + 8;
        #pragma unroll
        for (int j = 0; j < 4; j++) {
            int n = ncol + j * 8;
            *(float2*)(Sp + (size_t)ma * S_ + n) = make_float2(acc[i][j][0], acc[i][j][1]);
            *(float2*)(Sp + (size_t)mb * S_ + n) = make_float2(acc[i][j][2], acc[i][j][3]);
        }
    }
}

// ---------------- generic attention GEMM, occ2 ----------------
__global__ void __launch_bounds__(256, 2) hmma_gemm_k(
    const ushort_t* __restrict__ Ah, int lda,
    const ushort_t* __restrict__ Bh, int ldb,
    float* __restrict__ Cf, ushort_t* __restrict__ Ch,
    int ldc, int K, float alpha,
    const float* __restrict__ biasM, const float* __restrict__ biasN,
    const float* __restrict__ addend, int causal, int kcausal, int mrev) {
    const int by = mrev ? (gridDim.y - 1 - blockIdx.y) : blockIdx.y;
    const int m0 = by * 128, n0 = blockIdx.x * 128;
    if (causal && n0 >= (((m0 >> 10) + 1) << 10)) return;
    int Keff = kcausal ? (((m0 >> 10) + 1) << 10) : K;

    extern __shared__ unsigned char dynsm[];
    const uint32_t sm0 = smem_u32(dynsm);
    const int tid = threadIdx.x, lane = tid & 31, warp = tid >> 5;
    const int wm = warp & 1, wn = warp >> 1;

    HmmaAcc acc;
    #pragma unroll
    for (int i = 0; i < 4; i++)
        #pragma unroll
        for (int j = 0; j < 4; j++)
            #pragma unroll
            for (int r = 0; r < 4; r++) acc.a[i][j][r] = 0.f;

    hmma_mainloop(acc, sm0, tid, Ah, lda, Bh, ldb, m0, n0, Keff >> 5);

    const int mrow = m0 + wm * 64 + (lane >> 2);
    const int ncol = n0 + wn * 32 + (lane & 3) * 2;
    #pragma unroll
    for (int i = 0; i < 4; i++) {
        int ma = mrow + i * 16, mb = ma + 8;
        float bva = biasM ? biasM[ma] : 0.f;
        float bvb = biasM ? biasM[mb] : 0.f;
        #pragma unroll
        for (int j = 0; j < 4; j++) {
            int n = ncol + j * 8;
            float2 va = make_float2(acc.a[i][j][0] * alpha + bva, acc.a[i][j][1] * alpha + bva);
            float2 vb = make_float2(acc.a[i][j][2] * alpha + bvb, acc.a[i][j][3] * alpha + bvb);
            if (biasN) {
                float b0 = biasN[n], b1 = biasN[n + 1];
                va.x += b0; va.y += b1; vb.x += b0; vb.y += b1;
            }
            if (addend) {
                float2 aa = *(const float2*)(addend + (size_t)ma * ldc + n);
                float2 ab = *(const float2*)(addend + (size_t)mb * ldc + n);
                va.x += aa.x; va.y += aa.y; vb.x += ab.x; vb.y += ab.y;
            }
            if (Cf) {
                *(float2*)(Cf + (size_t)ma * ldc + n) = va;
                *(float2*)(Cf + (size_t)mb * ldc + n) = vb;
            }
            if (Ch) {
                *(ushort2*)(Ch + (size_t)ma * ldc + n) = make_ushort2(to_h(va.x), to_h(va.y));
                *(ushort2*)(Ch + (size_t)mb * ldc + n) = make_ushort2(to_h(vb.x), to_h(vb.y));
            }
        }
    }
}

// ---------------- softmax: single gmem pass via smem row buffer ----------------
__global__ void softmax_k() {
    __shared__ float row[S_];
    __shared__ float sh[8];
    int i = blockIdx.x;
    int L = ((i >> 10) + 1) << 10;
    const float4* src = (const float4*)(g_p + ((size_t)i << 13));
    int n4 = L >> 2;
    int tid = threadIdx.x;

    float mx = -1e30f;
    for (int j = tid; j < n4; j += 256) {
        float4 v = src[j];
        *(float4*)(row + 4 * j) = v;
        mx = fmaxf(mx, fmaxf(fmaxf(v.x, v.y), fmaxf(v.z, v.w)));
    }
    float wm = warp_max(mx);
    if ((tid & 31) == 0) sh[tid >> 5] = wm;
    __syncthreads();
    if (tid < 32) {
        float m2 = (tid < 8) ? sh[tid] : -1e30f;
        m2 = warp_max(m2);
        if (tid == 0) sh[0] = m2;
    }
    __syncthreads();
    float m = sh[0];
    __syncthreads();

    float s = 0.f;
    for (int j = tid; j < n4; j += 256) {
        float4 v = *(float4*)(row + 4 * j);
        v.x = __expf(v.x - m); v.y = __expf(v.y - m);
        v.z = __expf(v.z - m); v.w = __expf(v.w - m);
        s += v.x + v.y + v.z + v.w;
        *(float4*)(row + 4 * j) = v;
    }
    float ws = warp_sum(s);
    if ((tid & 31) == 0) sh[tid >> 5] = ws;
    __syncthreads();
    if (tid < 32) {
        float s2 = (tid < 8) ? sh[tid] : 0.f;
        s2 = warp_sum(s2);
        if (tid == 0) sh[0] = s2;
    }
    __syncthreads();
    float inv = 1.f / sh[0];
    size_t base = (size_t)i << 13;
    for (int j = tid; j < n4; j += 256) {
        float4 v = *(float4*)(row + 4 * j);
        uint2 hv = make_uint2(
            (uint32_t)to_h(v.x * inv) | ((uint32_t)to_h(v.y * inv) << 16),
            (uint32_t)to_h(v.z * inv) | ((uint32_t)to_h(v.w * inv) << 16));
        *(uint2*)(g_ph + base + 4 * (size_t)j) = hv;
    }
}

// ---------------- orchestration ----------------
extern "C" void kernel_launch(void* const* d_in, const int* in_sizes, int n_in,
                              void* d_out, int out_size) {
    (void)in_sizes; (void)n_in; (void)out_size;

    float *t1, *y0, *mid, *p;
    ushort_t *wah, *acth, *qh, *kh, *vh, *oh, *ph;
    cudaGetSymbolAddress((void**)&t1,   g_t1);
    cudaGetSymbolAddress((void**)&y0,   g_y0);
    cudaGetSymbolAddress((void**)&mid,  g_mid);
    cudaGetSymbolAddress((void**)&p,    g_p);
    cudaGetSymbolAddress((void**)&wah,  g_wah);
    cudaGetSymbolAddress((void**)&acth, g_ath);
    cudaGetSymbolAddress((void**)&qh,   g_qh);
    cudaGetSymbolAddress((void**)&kh,   g_kh);
    cudaGetSymbolAddress((void**)&vh,   g_vh);
    cudaGetSymbolAddress((void**)&oh,   g_oh);
    cudaGetSymbolAddress((void**)&ph,   g_ph);

    cudaFuncSetAttribute(conv_hmma_k, cudaFuncAttributeMaxDynamicSharedMemorySize, 4 * STG);
    cudaFuncSetAttribute(hmma_gemm_k, cudaFuncAttributeMaxDynamicSharedMemorySize, 3 * STG);
    cudaFuncSetAttribute(wpack_conv_k, cudaFuncAttributeMaxDynamicSharedMemorySize, KC * 4);

    const float* X = (const float*)d_in[0];
    const float* a_gns = (const float*)d_in[17];
    const float* a_gnb = (const float*)d_in[18];
    const float* a_wq  = (const float*)d_in[19];
    const float* a_bq  = (const float*)d_in[20];
    const float* a_wk  = (const float*)d_in[21];
    const float* a_bk  = (const float*)d_in[22];
    const float* a_wv  = (const float*)d_in[23];
    const float* a_bv  = (const float*)d_in[24];
    const float* a_wo  = (const float*)d_in[25];
    const float* a_bo  = (const float*)d_in[26];

    const dim3 conv_grid(16, 64);
    const dim3 nt_grid(S_ / 32, C_ / 32);
    const dim3 nt_blk(32, 8);
    const int WPACK_SQ = ((C_ * C_) / 8) / 256;

    auto resnet = [&](const float* in, int base, float* midb, float* outbuf,
                      int in_stats_from_part) {
        const float* n1s = (const float*)d_in[base + 0];
        const float* n1b = (const float*)d_in[base + 1];
        const float* w1  = (const float*)d_in[base + 2];
        const float* b1  = (const float*)d_in[base + 3];
        const float* n2s = (const float*)d_in[base + 4];
        const float* n2b = (const float*)d_in[base + 5];
        const float* w2  = (const float*)d_in[base + 6];
        const float* b2  = (const float*)d_in[base + 7];

        if (in_stats_from_part) gn_stats_p<<<NGROUP, 128>>>();
        else                    gn_stats_k<<<NGROUP, 256>>>(in);
        normact_t_k<<<nt_grid, nt_blk>>>(in, n1s, n1b, 1);
        wpack_conv_k<<<C_, 256, KC * 4>>>(w1);
        conv_hmma_k<<<conv_grid, 256, 4 * STG>>>();
        ksum_k<<<KSUM_BLOCKS, 256>>>(midb, b1, nullptr);
        gn_stats_p<<<NGROUP, 128>>>();
        normact_t_k<<<nt_grid, nt_blk>>>(midb, n2s, n2b, 1);
        wpack_conv_k<<<C_, 256, KC * 4>>>(w2);
        conv_hmma_k<<<conv_grid, 256, 4 * STG>>>();
        ksum_k<<<KSUM_BLOCKS, 256>>>(outbuf, b2, in);
    };

    // ---- ResNet block 0:  X -> y0 ----
    resnet(X, 1, t1, y0, 0);

    // ---- Causal frame attention on y0 (stats via ksum partials) ----
    gn_stats_p<<<NGROUP, 128>>>();
    normact_t_k<<<nt_grid, nt_blk>>>(y0, a_gns, a_gnb, 0);

    // Q[s][d] = act . wq^T + bq
    wpack_k<<<WPACK_SQ, 256>>>(a_wq, wah);
    hmma_gemm_k<<<dim3(4, 64), 256, 3 * STG>>>(acth, C_, wah, C_,
        nullptr, qh, C_, C_, 1.f, nullptr, a_bq, nullptr, 0, 0, 0);
    // K[s][d]
    wpack_k<<<WPACK_SQ, 256>>>(a_wk, wah);
    hmma_gemm_k<<<dim3(4, 64), 256, 3 * STG>>>(acth, C_, wah, C_,
        nullptr, kh, C_, C_, 1.f, nullptr, a_bk, nullptr, 0, 0, 0);
    // V[d][s] = wv . act^T + bv
    wpack_k<<<WPACK_SQ, 256>>>(a_wv, wah);
    hmma_gemm_k<<<dim3(64, 4), 256, 3 * STG>>>(wah, C_, acth, C_,
        nullptr, vh, S_, C_, 1.f, a_bv, nullptr, nullptr, 0, 0, 0);

    // scores: Q . K^T (block-causal tile skip)
    hmma_gemm_k<<<dim3(64, 64), 256, 3 * STG>>>(qh, C_, kh, C_,
        p, nullptr, S_, C_, 0.04419417382415922f,
        nullptr, nullptr, nullptr, 1, 0, 0);
    softmax_k<<<S_, 256>>>();
    // O[s][d] = P . V^T  (reversed m-order, causal K bound)
    hmma_gemm_k<<<dim3(4, 64), 256, 3 * STG>>>(ph, S_, vh, S_,
        nullptr, oh, C_, S_, 1.f, nullptr, nullptr, nullptr, 0, 1, 1);
    // attnout[c][s] = wo . O^T + bo + y0
    wpack_k<<<WPACK_SQ, 256>>>(a_wo, wah);
    hmma_gemm_k<<<dim3(64, 4), 256, 3 * STG>>>(wah, C_, oh, C_,
        t1, nullptr, S_, C_, 1.f, a_bo, nullptr, y0, 0, 0, 0);

    // ---- ResNet block 1:  t1 -> d_out ----
    resnet(t1, 9, mid, (float*)d_out, 0);
}

// round 15
// speedup vs baseline: 1.1383x; 1.0076x over previous
#include <cuda_runtime.h>
#include <cuda_fp16.h>
#include <math.h>
#include <stdint.h>

#define C_      512
#define S_      8192
#define HW_     1024
#define W_      32
#define NGROUP  32
#define CPG     16
#define KC      13824
#define NSPLIT  4
#define KSPLIT_ITERS 108      // (KC/32)/4
#define KSUM_BLOCKS 4096      // (C_*S_/4)/256

#define STG 16384             // GEMM smem stage: A 8K | B 8K

typedef unsigned short ushort_t;

__device__ float g_mean[NGROUP];
__device__ float g_rstd[NGROUP];
__device__ float2 g_part[KSUM_BLOCKS];
__device__ float g_t1 [(size_t)C_ * S_];
__device__ float g_y0 [(size_t)C_ * S_];
__device__ float g_mid[(size_t)C_ * S_];
__device__ float g_ks [(size_t)NSPLIT * C_ * S_];
__device__ __align__(16) ushort_t g_ath[(size_t)S_ * C_];    // normalized act [s][c]
__device__ __align__(16) ushort_t g_wh [(size_t)C_ * KC];    // conv weights, K = r*512+ci
__device__ __align__(16) ushort_t g_wah[(size_t)C_ * C_];
__device__ __align__(16) ushort_t g_qh [(size_t)S_ * C_];
__device__ __align__(16) ushort_t g_kh [(size_t)S_ * C_];
__device__ __align__(16) ushort_t g_vh [(size_t)C_ * S_];
__device__ __align__(16) ushort_t g_oh [(size_t)S_ * C_];
__device__ __align__(16) ushort_t g_ph [(size_t)S_ * S_];    // scores -> probs (fp16, in place)

// ---------------- PTX helpers ----------------
__device__ __forceinline__ uint32_t smem_u32(const void* p) {
    uint32_t a;
    asm("{ .reg .u64 t; cvta.to.shared.u64 t, %1; cvt.u32.u64 %0, t; }" : "=r"(a) : "l"(p));
    return a;
}
#define CP_ASYNC16(smem, gmem) \
    asm volatile("cp.async.cg.shared.global [%0], [%1], 16;" :: "r"(smem), "l"(gmem) : "memory")
#define CP_COMMIT() asm volatile("cp.async.commit_group;" ::: "memory")
#define CP_WAIT1()  asm volatile("cp.async.wait_group 1;" ::: "memory")
#define CP_WAIT2()  asm volatile("cp.async.wait_group 2;" ::: "memory")
#define LDSM4(r, addr) \
    asm volatile("ldmatrix.sync.aligned.m8n8.x4.shared.b16 {%0,%1,%2,%3}, [%4];" \
        : "=r"((r)[0]),"=r"((r)[1]),"=r"((r)[2]),"=r"((r)[3]) : "r"(addr))
#define MMA16816(d, a, b0, b1) \
    asm volatile("mma.sync.aligned.m16n8k16.row.col.f32.f16.f16.f32 " \
        "{%0,%1,%2,%3}, {%4,%5,%6,%7}, {%8,%9}, {%0,%1,%2,%3};" \
        : "+f"((d)[0]),"+f"((d)[1]),"+f"((d)[2]),"+f"((d)[3]) \
        : "r"((a)[0]),"r"((a)[1]),"r"((a)[2]),"r"((a)[3]), "r"(b0),"r"(b1))

__device__ __forceinline__ ushort_t to_h(float v) {
    return __half_as_ushort(__float2half_rn(v));
}
__device__ __forceinline__ float h2f(ushort_t h) {
    return __half2float(__ushort_as_half(h));
}

__inline__ __device__ float warp_sum(float v) {
    #pragma unroll
    for (int o = 16; o; o >>= 1) v += __shfl_down_sync(0xffffffffu, v, o);
    return v;
}
__inline__ __device__ float warp_max(float v) {
    #pragma unroll
    for (int o = 16; o; o >>= 1) v = fmaxf(v, __shfl_down_sync(0xffffffffu, v, o));
    return v;
}

// ---------------- GroupNorm stats (full read) ----------------
__global__ void gn_stats_k(const float* __restrict__ x) {
    int g = blockIdx.x;
    const float4* p = (const float4*)(x + (size_t)g * CPG * S_);
    const int n4 = (CPG * S_) / 4;
    float s = 0.f, s2 = 0.f;
    for (int i = threadIdx.x; i < n4; i += blockDim.x) {
        float4 v = p[i];
        s  += v.x + v.y + v.z + v.w;
        s2 += v.x * v.x + v.y * v.y + v.z * v.z + v.w * v.w;
    }
    __shared__ float sh0[8], sh1[8];
    float ws = warp_sum(s), ws2 = warp_sum(s2);
    int wid = threadIdx.x >> 5, lid = threadIdx.x & 31;
    if (!lid) { sh0[wid] = ws; sh1[wid] = ws2; }
    __syncthreads();
    if (threadIdx.x == 0) {
        float a = 0.f, b = 0.f;
        #pragma unroll
        for (int i = 0; i < 8; i++) { a += sh0[i]; b += sh1[i]; }
        const float inv_n = 1.f / (float)(CPG * S_);
        float m = a * inv_n;
        g_mean[g] = m;
        g_rstd[g] = rsqrtf(b * inv_n - m * m + 1e-6f);
    }
}

// ---------------- GroupNorm stats from ksum partials ----------------
__global__ void gn_stats_p() {
    int g = blockIdx.x;
    float2 v = g_part[g * 128 + threadIdx.x];
    __shared__ float sh0[4], sh1[4];
    float ws = warp_sum(v.x), ws2 = warp_sum(v.y);
    int wid = threadIdx.x >> 5, lid = threadIdx.x & 31;
    if (!lid) { sh0[wid] = ws; sh1[wid] = ws2; }
    __syncthreads();
    if (threadIdx.x == 0) {
        float a = sh0[0] + sh0[1] + sh0[2] + sh0[3];
        float b = sh1[0] + sh1[1] + sh1[2] + sh1[3];
        const float inv_n = 1.f / (float)(CPG * S_);
        float m = a * inv_n;
        g_mean[g] = m;
        g_rstd[g] = rsqrtf(b * inv_n - m * m + 1e-6f);
    }
}

// ---------------- transposing GN (+optional SiLU): x [c][s] -> fp16 [s][c] ------
__global__ void normact_t_k(const float* __restrict__ x, const float* __restrict__ sc,
                            const float* __restrict__ bi, int do_silu) {
    __shared__ float tile[32][33];
    int s0 = blockIdx.x * 32, c0 = blockIdx.y * 32;
    int tx = threadIdx.x, ty = threadIdx.y;
    #pragma unroll
    for (int i = ty; i < 32; i += 8)
        tile[i][tx] = x[(size_t)(c0 + i) * S_ + s0 + tx];
    __syncthreads();
    int c = c0 + tx;
    int g = c >> 4;
    float mu = g_mean[g], rs = g_rstd[g], sv = sc[c], bv = bi[c];
    #pragma unroll
    for (int i = ty; i < 32; i += 8) {
        float v = (tile[tx][i] - mu) * rs * sv + bv;
        if (do_silu) v = v / (1.f + __expf(-v));
        g_ath[(size_t)(s0 + i) * C_ + c] = to_h(v);
    }
}

// ---------------- conv weight pack (smem transpose, contiguous reads) ----------
__global__ void wpack_conv_k(const float* __restrict__ w) {
    extern __shared__ float buf[];
    int co = blockIdx.x;
    const float4* src = (const float4*)(w + (size_t)co * KC);
    for (int i = threadIdx.x; i < KC / 4; i += 256)
        *(float4*)&buf[i * 4] = src[i];
    __syncthreads();
    for (int i = threadIdx.x; i < KC / 8; i += 256) {
        int kk = i * 8;
        int r = kk >> 9, ci0 = kk & 511;
        __align__(16) ushort_t hv[8];
        #pragma unroll
        for (int e = 0; e < 8; e++)
            hv[e] = to_h(buf[(ci0 + e) * 27 + r]);
        *(uint4*)(g_wh + (size_t)co * KC + kk) = *(uint4*)hv;
    }
}

// ---------------- pack: fp32 row-major -> fp16 (attention weights) ----------------
__global__ void wpack_k(const float* __restrict__ w, ushort_t* __restrict__ dh) {
    size_t id = (size_t)blockIdx.x * 256 + threadIdx.x;
    const float4* src = (const float4*)w;
    float4 v0 = src[id * 2], v1 = src[id * 2 + 1];
    __align__(16) ushort_t hv[8];
    hv[0] = to_h(v0.x); hv[1] = to_h(v0.y); hv[2] = to_h(v0.z); hv[3] = to_h(v0.w);
    hv[4] = to_h(v1.x); hv[5] = to_h(v1.y); hv[6] = to_h(v1.z); hv[7] = to_h(v1.w);
    *(uint4*)(dh + id * 8) = *(uint4*)hv;
}

// ---------------- split-K reduce + per-block GN partials ----------------
__global__ void ksum_k(float* __restrict__ out, const float* __restrict__ bias,
                       const float* __restrict__ addend) {
    size_t i = ((size_t)blockIdx.x * 256 + threadIdx.x) * 4;
    int c = (int)(i >> 13);
    float4 v0 = *(const float4*)(g_ks + i);
    float4 v1 = *(const float4*)(g_ks + (size_t)C_ * S_ + i);
    float4 v2 = *(const float4*)(g_ks + (size_t)2 * C_ * S_ + i);
    float4 v3 = *(const float4*)(g_ks + (size_t)3 * C_ * S_ + i);
    float bv = bias[c];
    float4 r;
    r.x = v0.x + v1.x + v2.x + v3.x + bv;
    r.y = v0.y + v1.y + v2.y + v3.y + bv;
    r.z = v0.z + v1.z + v2.z + v3.z + bv;
    r.w = v0.w + v1.w + v2.w + v3.w + bv;
    if (addend) {
        float4 a = *(const float4*)(addend + i);
        r.x += a.x; r.y += a.y; r.z += a.z; r.w += a.w;
    }
    *(float4*)(out + i) = r;
    float s  = r.x + r.y + r.z + r.w;
    float s2 = r.x * r.x + r.y * r.y + r.z * r.z + r.w * r.w;
    __shared__ float sh0[8], sh1[8];
    float ws = warp_sum(s), ws2 = warp_sum(s2);
    int wid = threadIdx.x >> 5, lid = threadIdx.x & 31;
    if (!lid) { sh0[wid] = ws; sh1[wid] = ws2; }
    __syncthreads();
    if (threadIdx.x == 0) {
        float a = 0.f, b = 0.f;
        #pragma unroll
        for (int k = 0; k < 8; k++) { a += sh0[k]; b += sh1[k]; }
        g_part[blockIdx.x] = make_float2(a, b);
    }
}

// ================= attention HMMA mainloop (3-stage, 1 sync/iter) =================
struct HmmaAcc { float a[4][4][4]; };

__device__ __forceinline__ void hmma_mainloop(
    HmmaAcc& A4, uint32_t sm0, int tid,
    const ushort_t* __restrict__ Ah, int lda,
    const ushort_t* __restrict__ Bh, int ldb,
    int m0, int n0, int kiters) {
    const int lane = tid & 31, warp = tid >> 5;
    const int wm = warp & 1, wn = warp >> 1;

    auto issue = [&](int stage, int k0) {
        uint32_t sb = sm0 + stage * STG;
        #pragma unroll
        for (int h = 0; h < 2; h++) {
            int id = tid + h * 256;
            int r = id >> 2, cu = id & 3;
            uint32_t soff = r * 64 + (((cu ^ ((r >> 1) & 3))) << 4);
            CP_ASYNC16(sb + soff,        Ah + (size_t)(m0 + r) * lda + k0 + cu * 8);
            CP_ASYNC16(sb + 8192 + soff, Bh + (size_t)(n0 + r) * ldb + k0 + cu * 8);
        }
        CP_COMMIT();
    };

    issue(0, 0);
    issue(1, 32);

    const int rl = lane & 15, ul = lane >> 4;
    for (int it = 0; it < kiters; it++) {
        CP_WAIT1();
        __syncthreads();
        if (it + 2 < kiters) issue((it + 2) % 3, (it + 2) * 32);
        else CP_COMMIT();
        uint32_t sb = sm0 + (it % 3) * STG;
        #pragma unroll
        for (int k16 = 0; k16 < 2; k16++) {
            uint32_t a4[4][4], b4[2][4];
            int u = k16 * 2 + ul;
            #pragma unroll
            for (int i = 0; i < 4; i++) {
                int r = wm * 64 + i * 16 + rl;
                LDSM4(a4[i], sb + r * 64 + (((u ^ ((r >> 1) & 3))) << 4));
            }
            #pragma unroll
            for (int j2 = 0; j2 < 2; j2++) {
                int r = wn * 32 + j2 * 16 + rl;
                LDSM4(b4[j2], sb + 8192 + r * 64 + (((u ^ ((r >> 1) & 3))) << 4));
            }
            #pragma unroll
            for (int i = 0; i < 4; i++)
                #pragma unroll
                for (int j = 0; j < 4; j++) {
                    int j2 = j >> 1, ts = j & 1;
                    MMA16816(A4.a[i][j], a4[i], b4[j2][ts], b4[j2][ts + 2]);
                }
        }
    }
}

// ---------------- conv GEMM: implicit gather, split-K, 4-stage, occ2 ----------
// grid (16, 64): x -> m-tile (x&3), ksplit (x>>2); y -> n-tile. 256 threads.
__global__ void __launch_bounds__(256, 2) conv_hmma_k() {
    extern __shared__ unsigned char dynsm[];
    const uint32_t sm0 = smem_u32(dynsm);
    const int tid = threadIdx.x, lane = tid & 31, warp = tid >> 5;
    const int m0 = (blockIdx.x & 3) * 128;
    const int ks = blockIdx.x >> 2;
    const int n0 = blockIdx.y * 128;
    const int kbase = ks * (KSPLIT_ITERS * 32);
    const int wm = warp & 1, wn = warp >> 1;

    int rrow[2], cu8[2];
    uint32_t soffv[2];
    int tm2[2], ym1[2], xm1[2];
    #pragma unroll
    for (int h = 0; h < 2; h++) {
        int id = tid + h * 256;
        int r = id >> 2, cu = id & 3;
        rrow[h] = r; cu8[h] = cu * 8;
        soffv[h] = r * 64 + (((cu ^ ((r >> 1) & 3))) << 4);
        int pos = n0 + r;
        tm2[h] = (pos >> 10) - 2;
        ym1[h] = ((pos >> 5) & 31) - 1;
        xm1[h] = (pos & 31) - 1;
    }

    auto issue = [&](int stage, int k0) {
        uint32_t sb = sm0 + stage * STG;
        int rcode = k0 >> 9;
        int ci0 = k0 & 511;
        int kd = rcode / 9;
        int rr = rcode - kd * 9;
        int kh = rr / 3;
        int kw = rr - kh * 3;
        #pragma unroll
        for (int h = 0; h < 2; h++) {
            CP_ASYNC16(sb + soffv[h],
                       g_wh + (size_t)(m0 + rrow[h]) * KC + k0 + cu8[h]);
            int ts = min(max(tm2[h] + kd, 0), 7);
            int ys = min(max(ym1[h] + kh, 0), 31);
            int xs = min(max(xm1[h] + kw, 0), 31);
            CP_ASYNC16(sb + 8192 + soffv[h],
                       g_ath + (size_t)((ts << 10) + (ys << 5) + xs) * C_ + ci0 + cu8[h]);
        }
        CP_COMMIT();
    };

    float acc[4][4][4];
    #pragma unroll
    for (int i = 0; i < 4; i++)
        #pragma unroll
        for (int j = 0; j < 4; j++)
            #pragma unroll
            for (int r = 0; r < 4; r++) acc[i][j][r] = 0.f;

    issue(0, kbase);
    issue(1, kbase + 32);
    issue(2, kbase + 64);

    const int rl = lane & 15, ul = lane >> 4;
    for (int it = 0; it < KSPLIT_ITERS; it++) {
        CP_WAIT2();
        __syncthreads();
        if (it + 3 < KSPLIT_ITERS) issue((it + 3) & 3, kbase + (it + 3) * 32);
        else CP_COMMIT();
        uint32_t sb = sm0 + (it & 3) * STG;
        #pragma unroll
        for (int k16 = 0; k16 < 2; k16++) {
            uint32_t a4[4][4], b4[2][4];
            int u = k16 * 2 + ul;
            #pragma unroll
            for (int i = 0; i < 4; i++) {
                int r = wm * 64 + i * 16 + rl;
                LDSM4(a4[i], sb + r * 64 + (((u ^ ((r >> 1) & 3))) << 4));
            }
            #pragma unroll
            for (int j2 = 0; j2 < 2; j2++) {
                int r = wn * 32 + j2 * 16 + rl;
                LDSM4(b4[j2], sb + 8192 + r * 64 + (((u ^ ((r >> 1) & 3))) << 4));
            }
            #pragma unroll
            for (int i = 0; i < 4; i++)
                #pragma unroll
                for (int j = 0; j < 4; j++) {
                    int j2 = j >> 1, ts = j & 1;
                    MMA16816(acc[i][j], a4[i], b4[j2][ts], b4[j2][ts + 2]);
                }
        }
    }

    float* Sp = g_ks + (size_t)ks * C_ * S_;
    const int mrow = m0 + wm * 64 + (lane >> 2);
    const int ncol = n0 + wn * 32 + (lane & 3) * 2;
    #pragma unroll
    for (int i = 0; i < 4; i++) {
        int ma = mrow + i * 16, mb = ma + 8;
        #pragma unroll
        for (int j = 0; j < 4; j++) {
            int n = ncol + j * 8;
            *(float2*)(Sp + (size_t)ma * S_ + n) = make_float2(acc[i][j][0], acc[i][j][1]);
            *(float2*)(Sp + (size_t)mb * S_ + n) = make_float2(acc[i][j][2], acc[i][j][3]);
        }
    }
}

// ---------------- generic attention GEMM, occ2 ----------------
__global__ void __launch_bounds__(256, 2) hmma_gemm_k(
    const ushort_t* __restrict__ Ah, int lda,
    const ushort_t* __restrict__ Bh, int ldb,
    float* __restrict__ Cf, ushort_t* __restrict__ Ch,
    int ldc, int K, float alpha,
    const float* __restrict__ biasM, const float* __restrict__ biasN,
    const float* __restrict__ addend, int causal, int kcausal, int mrev) {
    const int by = mrev ? (gridDim.y - 1 - blockIdx.y) : blockIdx.y;
    const int m0 = by * 128, n0 = blockIdx.x * 128;
    if (causal && n0 >= (((m0 >> 10) + 1) << 10)) return;
    int Keff = kcausal ? (((m0 >> 10) + 1) << 10) : K;

    extern __shared__ unsigned char dynsm[];
    const uint32_t sm0 = smem_u32(dynsm);
    const int tid = threadIdx.x, lane = tid & 31, warp = tid >> 5;
    const int wm = warp & 1, wn = warp >> 1;

    HmmaAcc acc;
    #pragma unroll
    for (int i = 0; i < 4; i++)
        #pragma unroll
        for (int j = 0; j < 4; j++)
            #pragma unroll
            for (int r = 0; r < 4; r++) acc.a[i][j][r] = 0.f;

    hmma_mainloop(acc, sm0, tid, Ah, lda, Bh, ldb, m0, n0, Keff >> 5);

    const int mrow = m0 + wm * 64 + (lane >> 2);
    const int ncol = n0 + wn * 32 + (lane & 3) * 2;
    #pragma unroll
    for (int i = 0; i < 4; i++) {
        int ma = mrow + i * 16, mb = ma + 8;
        float bva = biasM ? biasM[ma] : 0.f;
        float bvb = biasM ? biasM[mb] : 0.f;
        #pragma unroll
        for (int j = 0; j < 4; j++) {
            int n = ncol + j * 8;
            float2 va = make_float2(acc.a[i][j][0] * alpha + bva, acc.a[i][j][1] * alpha + bva);
            float2 vb = make_float2(acc.a[i][j][2] * alpha + bvb, acc.a[i][j][3] * alpha + bvb);
            if (biasN) {
                float b0 = biasN[n], b1 = biasN[n + 1];
                va.x += b0; va.y += b1; vb.x += b0; vb.y += b1;
            }
            if (addend) {
                float2 aa = *(const float2*)(addend + (size_t)ma * ldc + n);
                float2 ab = *(const float2*)(addend + (size_t)mb * ldc + n);
                va.x += aa.x; va.y += aa.y; vb.x += ab.x; vb.y += ab.y;
            }
            if (Cf) {
                *(float2*)(Cf + (size_t)ma * ldc + n) = va;
                *(float2*)(Cf + (size_t)mb * ldc + n) = vb;
            }
            if (Ch) {
                *(ushort2*)(Ch + (size_t)ma * ldc + n) = make_ushort2(to_h(va.x), to_h(va.y));
                *(ushort2*)(Ch + (size_t)mb * ldc + n) = make_ushort2(to_h(vb.x), to_h(vb.y));
            }
        }
    }
}

// ---------------- softmax: fp16 scores in g_ph -> fp16 probs in place ----------
// reversed row order: longest causal rows launch first
__global__ void softmax_k() {
    __shared__ float row[S_];
    __shared__ float sh[8];
    int i = (S_ - 1) - blockIdx.x;
    int L = ((i >> 10) + 1) << 10;
    ushort_t* rp = g_ph + ((size_t)i << 13);
    int n4 = L >> 2;
    int tid = threadIdx.x;

    float mx = -1e30f;
    for (int j = tid; j < n4; j += 256) {
        uint2 hv = *(const uint2*)(rp + 4 * (size_t)j);
        float2 f0 = __half22float2(*(__half2*)&hv.x);
        float2 f1 = __half22float2(*(__half2*)&hv.y);
        row[4 * j + 0] = f0.x; row[4 * j + 1] = f0.y;
        row[4 * j + 2] = f1.x; row[4 * j + 3] = f1.y;
        mx = fmaxf(mx, fmaxf(fmaxf(f0.x, f0.y), fmaxf(f1.x, f1.y)));
    }
    float wm = warp_max(mx);
    if ((tid & 31) == 0) sh[tid >> 5] = wm;
    __syncthreads();
    if (tid < 32) {
        float m2 = (tid < 8) ? sh[tid] : -1e30f;
        m2 = warp_max(m2);
        if (tid == 0) sh[0] = m2;
    }
    __syncthreads();
    float m = sh[0];
    __syncthreads();

    float s = 0.f;
    for (int j = tid; j < n4; j += 256) {
        float4 v = *(float4*)(row + 4 * j);
        v.x = __expf(v.x - m); v.y = __expf(v.y - m);
        v.z = __expf(v.z - m); v.w = __expf(v.w - m);
        s += v.x + v.y + v.z + v.w;
        *(float4*)(row + 4 * j) = v;
    }
    float ws = warp_sum(s);
    if ((tid & 31) == 0) sh[tid >> 5] = ws;
    __syncthreads();
    if (tid < 32) {
        float s2 = (tid < 8) ? sh[tid] : 0.f;
        s2 = warp_sum(s2);
        if (tid == 0) sh[0] = s2;
    }
    __syncthreads();
    float inv = 1.f / sh[0];
    for (int j = tid; j < n4; j += 256) {
        float4 v = *(float4*)(row + 4 * j);
        uint2 hv = make_uint2(
            (uint32_t)to_h(v.x * inv) | ((uint32_t)to_h(v.y * inv) << 16),
            (uint32_t)to_h(v.z * inv) | ((uint32_t)to_h(v.w * inv) << 16));
        *(uint2*)(rp + 4 * (size_t)j) = hv;
    }
}

// ---------------- orchestration ----------------
extern "C" void kernel_launch(void* const* d_in, const int* in_sizes, int n_in,
                              void* d_out, int out_size) {
    (void)in_sizes; (void)n_in; (void)out_size;

    float *t1, *y0, *mid;
    ushort_t *wah, *acth, *qh, *kh, *vh, *oh, *ph;
    cudaGetSymbolAddress((void**)&t1,   g_t1);
    cudaGetSymbolAddress((void**)&y0,   g_y0);
    cudaGetSymbolAddress((void**)&mid,  g_mid);
    cudaGetSymbolAddress((void**)&wah,  g_wah);
    cudaGetSymbolAddress((void**)&acth, g_ath);
    cudaGetSymbolAddress((void**)&qh,   g_qh);
    cudaGetSymbolAddress((void**)&kh,   g_kh);
    cudaGetSymbolAddress((void**)&vh,   g_vh);
    cudaGetSymbolAddress((void**)&oh,   g_oh);
    cudaGetSymbolAddress((void**)&ph,   g_ph);

    cudaFuncSetAttribute(conv_hmma_k, cudaFuncAttributeMaxDynamicSharedMemorySize, 4 * STG);
    cudaFuncSetAttribute(hmma_gemm_k, cudaFuncAttributeMaxDynamicSharedMemorySize, 3 * STG);
    cudaFuncSetAttribute(wpack_conv_k, cudaFuncAttributeMaxDynamicSharedMemorySize, KC * 4);

    const float* X = (const float*)d_in[0];
    const float* a_gns = (const float*)d_in[17];
    const float* a_gnb = (const float*)d_in[18];
    const float* a_wq  = (const float*)d_in[19];
    const float* a_bq  = (const float*)d_in[20];
    const float* a_wk  = (const float*)d_in[21];
    const float* a_bk  = (const float*)d_in[22];
    const float* a_wv  = (const float*)d_in[23];
    const float* a_bv  = (const float*)d_in[24];
    const float* a_wo  = (const float*)d_in[25];
    const float* a_bo  = (const float*)d_in[26];

    const dim3 conv_grid(16, 64);
    const dim3 nt_grid(S_ / 32, C_ / 32);
    const dim3 nt_blk(32, 8);
    const int WPACK_SQ = ((C_ * C_) / 8) / 256;

    auto resnet = [&](const float* in, int base, float* midb, float* outbuf,
                      int in_stats_from_part) {
        const float* n1s = (const float*)d_in[base + 0];
        const float* n1b = (const float*)d_in[base + 1];
        const float* w1  = (const float*)d_in[base + 2];
        const float* b1  = (const float*)d_in[base + 3];
        const float* n2s = (const float*)d_in[base + 4];
        const float* n2b = (const float*)d_in[base + 5];
        const float* w2  = (const float*)d_in[base + 6];
        const float* b2  = (const float*)d_in[base + 7];

        if (in_stats_from_part) gn_stats_p<<<NGROUP, 128>>>();
        else                    gn_stats_k<<<NGROUP, 256>>>(in);
        normact_t_k<<<nt_grid, nt_blk>>>(in, n1s, n1b, 1);
        wpack_conv_k<<<C_, 256, KC * 4>>>(w1);
        conv_hmma_k<<<conv_grid, 256, 4 * STG>>>();
        ksum_k<<<KSUM_BLOCKS, 256>>>(midb, b1, nullptr);
        gn_stats_p<<<NGROUP, 128>>>();
        normact_t_k<<<nt_grid, nt_blk>>>(midb, n2s, n2b, 1);
        wpack_conv_k<<<C_, 256, KC * 4>>>(w2);
        conv_hmma_k<<<conv_grid, 256, 4 * STG>>>();
        ksum_k<<<KSUM_BLOCKS, 256>>>(outbuf, b2, in);
    };

    // ---- ResNet block 0:  X -> y0 ----
    resnet(X, 1, t1, y0, 0);

    // ---- Causal frame attention on y0 (stats via ksum partials) ----
    gn_stats_p<<<NGROUP, 128>>>();
    normact_t_k<<<nt_grid, nt_blk>>>(y0, a_gns, a_gnb, 0);

    // Q[s][d] = act . wq^T + bq
    wpack_k<<<WPACK_SQ, 256>>>(a_wq, wah);
    hmma_gemm_k<<<dim3(4, 64), 256, 3 * STG>>>(acth, C_, wah, C_,
        nullptr, qh, C_, C_, 1.f, nullptr, a_bq, nullptr, 0, 0, 0);
    // K[s][d]
    wpack_k<<<WPACK_SQ, 256>>>(a_wk, wah);
    hmma_gemm_k<<<dim3(4, 64), 256, 3 * STG>>>(acth, C_, wah, C_,
        nullptr, kh, C_, C_, 1.f, nullptr, a_bk, nullptr, 0, 0, 0);
    // V[d][s] = wv . act^T + bv
    wpack_k<<<WPACK_SQ, 256>>>(a_wv, wah);
    hmma_gemm_k<<<dim3(64, 4), 256, 3 * STG>>>(wah, C_, acth, C_,
        nullptr, vh, S_, C_, 1.f, a_bv, nullptr, nullptr, 0, 0, 0);

    // scores (fp16 out): Q . K^T (block-causal tile skip)
    hmma_gemm_k<<<dim3(64, 64), 256, 3 * STG>>>(qh, C_, kh, C_,
        nullptr, ph, S_, C_, 0.04419417382415922f,
        nullptr, nullptr, nullptr, 1, 0, 0);
    softmax_k<<<S_, 256>>>();
    // O[s][d] = P . V^T  (reversed m-order, causal K bound)
    hmma_gemm_k<<<dim3(4, 64), 256, 3 * STG>>>(ph, S_, vh, S_,
        nullptr, oh, C_, S_, 1.f, nullptr, nullptr, nullptr, 0, 1, 1);
    // attnout[c][s] = wo . O^T + bo + y0
    wpack_k<<<WPACK_SQ, 256>>>(a_wo, wah);
    hmma_gemm_k<<<dim3(64, 4), 256, 3 * STG>>>(wah, C_, oh, C_,
        t1, nullptr, S_, C_, 1.f, a_bo, nullptr, y0, 0, 0, 0);

    // ---- ResNet block 1:  t1 -> d_out ----
    resnet(t1, 9, mid, (float*)d_out, 0);
}

// round 16
// speedup vs baseline: 1.1393x; 1.0009x over previous
#include <cuda_runtime.h>
#include <cuda_fp16.h>
#include <math.h>
#include <stdint.h>

#define C_      512
#define S_      8192
#define HW_     1024
#define W_      32
#define NGROUP  32
#define CPG     16
#define KC      13824
#define NSPLIT  4
#define KSPLIT_ITERS 108      // (KC/32)/4
#define KSUM_BLOCKS 4096      // (C_*S_/4)/256

#define STG 16384             // GEMM smem stage: A 8K | B 8K

typedef unsigned short ushort_t;

__device__ float g_mean[NGROUP];
__device__ float g_rstd[NGROUP];
__device__ float2 g_part[KSUM_BLOCKS];
__device__ float g_t1 [(size_t)C_ * S_];
__device__ float g_y0 [(size_t)C_ * S_];
__device__ float g_mid[(size_t)C_ * S_];
__device__ float g_ks [(size_t)NSPLIT * C_ * S_];
__device__ __align__(16) ushort_t g_ath[(size_t)S_ * C_];    // normalized act [s][c]
__device__ __align__(16) ushort_t g_wh [(size_t)C_ * KC];    // conv weights, K = r*512+ci
__device__ __align__(16) ushort_t g_wqk[(size_t)1024 * C_];  // wq || wk
__device__ __align__(16) ushort_t g_wah[(size_t)C_ * C_];    // wv
__device__ __align__(16) ushort_t g_woh[(size_t)C_ * C_];    // wo
__device__ __align__(16) ushort_t g_qkh[(size_t)S_ * 1024];  // Q||K [s][1024]
__device__ __align__(16) ushort_t g_vh [(size_t)C_ * S_];
__device__ __align__(16) ushort_t g_oh [(size_t)S_ * C_];
__device__ __align__(16) ushort_t g_ph [(size_t)S_ * S_];    // scores -> probs (fp16)

// ---------------- PTX helpers ----------------
__device__ __forceinline__ uint32_t smem_u32(const void* p) {
    uint32_t a;
    asm("{ .reg .u64 t; cvta.to.shared.u64 t, %1; cvt.u32.u64 %0, t; }" : "=r"(a) : "l"(p));
    return a;
}
#define CP_ASYNC16(smem, gmem) \
    asm volatile("cp.async.cg.shared.global [%0], [%1], 16;" :: "r"(smem), "l"(gmem) : "memory")
#define CP_COMMIT() asm volatile("cp.async.commit_group;" ::: "memory")
#define CP_WAIT1()  asm volatile("cp.async.wait_group 1;" ::: "memory")
#define CP_WAIT2()  asm volatile("cp.async.wait_group 2;" ::: "memory")
#define LDSM4(r, addr) \
    asm volatile("ldmatrix.sync.aligned.m8n8.x4.shared.b16 {%0,%1,%2,%3}, [%4];" \
        : "=r"((r)[0]),"=r"((r)[1]),"=r"((r)[2]),"=r"((r)[3]) : "r"(addr))
#define MMA16816(d, a, b0, b1) \
    asm volatile("mma.sync.aligned.m16n8k16.row.col.f32.f16.f16.f32 " \
        "{%0,%1,%2,%3}, {%4,%5,%6,%7}, {%8,%9}, {%0,%1,%2,%3};" \
        : "+f"((d)[0]),"+f"((d)[1]),"+f"((d)[2]),"+f"((d)[3]) \
        : "r"((a)[0]),"r"((a)[1]),"r"((a)[2]),"r"((a)[3]), "r"(b0),"r"(b1))

__device__ __forceinline__ ushort_t to_h(float v) {
    return __half_as_ushort(__float2half_rn(v));
}

__inline__ __device__ float warp_sum(float v) {
    #pragma unroll
    for (int o = 16; o; o >>= 1) v += __shfl_down_sync(0xffffffffu, v, o);
    return v;
}
__inline__ __device__ float warp_max(float v) {
    #pragma unroll
    for (int o = 16; o; o >>= 1) v = fmaxf(v, __shfl_down_sync(0xffffffffu, v, o));
    return v;
}

// ---------------- GroupNorm stats (full read; for X and t1) ----------------
__global__ void gn_stats_k(const float* __restrict__ x) {
    int g = blockIdx.x;
    const float4* p = (const float4*)(x + (size_t)g * CPG * S_);
    const int n4 = (CPG * S_) / 4;
    float s = 0.f, s2 = 0.f;
    for (int i = threadIdx.x; i < n4; i += blockDim.x) {
        float4 v = p[i];
        s  += v.x + v.y + v.z + v.w;
        s2 += v.x * v.x + v.y * v.y + v.z * v.z + v.w * v.w;
    }
    __shared__ float sh0[8], sh1[8];
    float ws = warp_sum(s), ws2 = warp_sum(s2);
    int wid = threadIdx.x >> 5, lid = threadIdx.x & 31;
    if (!lid) { sh0[wid] = ws; sh1[wid] = ws2; }
    __syncthreads();
    if (threadIdx.x == 0) {
        float a = 0.f, b = 0.f;
        #pragma unroll
        for (int i = 0; i < 8; i++) { a += sh0[i]; b += sh1[i]; }
        const float inv_n = 1.f / (float)(CPG * S_);
        float m = a * inv_n;
        g_mean[g] = m;
        g_rstd[g] = rsqrtf(b * inv_n - m * m + 1e-6f);
    }
}

// ---------------- transposing GN (+optional SiLU): x [c][s] -> fp16 [s][c] ------
// part != 0: compute stats inline from ksum partials (2 groups per block).
__global__ void normact_t_k(const float* __restrict__ x, const float* __restrict__ sc,
                            const float* __restrict__ bi, int do_silu,
                            const float2* __restrict__ part) {
    __shared__ float tile[32][33];
    __shared__ float sa[8], sb[8], smu[2], srs[2];
    int s0 = blockIdx.x * 32, c0 = blockIdx.y * 32;
    int tx = threadIdx.x, ty = threadIdx.y;
    int tid = ty * 32 + tx;
    #pragma unroll
    for (int i = ty; i < 32; i += 8)
        tile[i][tx] = x[(size_t)(c0 + i) * S_ + s0 + tx];
    if (part) {
        int sel = tid >> 7, idx = tid & 127;       // warps 0-3: group c0/16; 4-7: +1
        float2 v = part[(size_t)(((c0 >> 4) + sel) * 128 + idx)];
        float ws = warp_sum(v.x), ws2 = warp_sum(v.y);
        if ((tid & 31) == 0) { sa[tid >> 5] = ws; sb[tid >> 5] = ws2; }
    }
    __syncthreads();
    if (part && tid < 2) {
        float a = sa[tid * 4] + sa[tid * 4 + 1] + sa[tid * 4 + 2] + sa[tid * 4 + 3];
        float b = sb[tid * 4] + sb[tid * 4 + 1] + sb[tid * 4 + 2] + sb[tid * 4 + 3];
        const float inv_n = 1.f / (float)(CPG * S_);
        float m = a * inv_n;
        smu[tid] = m;
        srs[tid] = rsqrtf(b * inv_n - m * m + 1e-6f);
    }
    __syncthreads();
    int c = c0 + tx;
    float mu, rs;
    if (part) { int sel2 = tx >> 4; mu = smu[sel2]; rs = srs[sel2]; }
    else      { int g = c >> 4;     mu = g_mean[g]; rs = g_rstd[g]; }
    float sv = sc[c], bv = bi[c];
    #pragma unroll
    for (int i = ty; i < 32; i += 8) {
        float v = (tile[tx][i] - mu) * rs * sv + bv;
        if (do_silu) v = v / (1.f + __expf(-v));
        g_ath[(size_t)(s0 + i) * C_ + c] = to_h(v);
    }
}

// ---------------- conv weight pack (smem transpose, contiguous reads) ----------
__global__ void wpack_conv_k(const float* __restrict__ w) {
    extern __shared__ float buf[];
    int co = blockIdx.x;
    const float4* src = (const float4*)(w + (size_t)co * KC);
    for (int i = threadIdx.x; i < KC / 4; i += 256)
        *(float4*)&buf[i * 4] = src[i];
    __syncthreads();
    for (int i = threadIdx.x; i < KC / 8; i += 256) {
        int kk = i * 8;
        int r = kk >> 9, ci0 = kk & 511;
        __align__(16) ushort_t hv[8];
        #pragma unroll
        for (int e = 0; e < 8; e++)
            hv[e] = to_h(buf[(ci0 + e) * 27 + r]);
        *(uint4*)(g_wh + (size_t)co * KC + kk) = *(uint4*)hv;
    }
}

// ---------------- batched attention weight pack: wq||wk -> g_wqk, wv, wo --------
__global__ void wpack_all_k(const float* __restrict__ wq, const float* __restrict__ wk,
                            const float* __restrict__ wv, const float* __restrict__ wo) {
    int which = blockIdx.y;
    const float* w = (which == 0) ? wq : (which == 1) ? wk : (which == 2) ? wv : wo;
    ushort_t* dst = (which == 0) ? g_wqk
                  : (which == 1) ? g_wqk + (size_t)512 * C_
                  : (which == 2) ? g_wah : g_woh;
    size_t id = (size_t)blockIdx.x * 256 + threadIdx.x;     // over C_*C_/8
    const float4* src = (const float4*)w;
    float4 v0 = src[id * 2], v1 = src[id * 2 + 1];
    __align__(16) ushort_t hv[8];
    hv[0] = to_h(v0.x); hv[1] = to_h(v0.y); hv[2] = to_h(v0.z); hv[3] = to_h(v0.w);
    hv[4] = to_h(v1.x); hv[5] = to_h(v1.y); hv[6] = to_h(v1.z); hv[7] = to_h(v1.w);
    *(uint4*)(dst + id * 8) = *(uint4*)hv;
}

// ---------------- split-K reduce + per-block GN partials ----------------
__global__ void ksum_k(float* __restrict__ out, const float* __restrict__ bias,
                       const float* __restrict__ addend) {
    size_t i = ((size_t)blockIdx.x * 256 + threadIdx.x) * 4;
    int c = (int)(i >> 13);
    float4 v0 = *(const float4*)(g_ks + i);
    float4 v1 = *(const float4*)(g_ks + (size_t)C_ * S_ + i);
    float4 v2 = *(const float4*)(g_ks + (size_t)2 * C_ * S_ + i);
    float4 v3 = *(const float4*)(g_ks + (size_t)3 * C_ * S_ + i);
    float bv = bias[c];
    float4 r;
    r.x = v0.x + v1.x + v2.x + v3.x + bv;
    r.y = v0.y + v1.y + v2.y + v3.y + bv;
    r.z = v0.z + v1.z + v2.z + v3.z + bv;
    r.w = v0.w + v1.w + v2.w + v3.w + bv;
    if (addend) {
        float4 a = *(const float4*)(addend + i);
        r.x += a.x; r.y += a.y; r.z += a.z; r.w += a.w;
    }
    *(float4*)(out + i) = r;
    float s  = r.x + r.y + r.z + r.w;
    float s2 = r.x * r.x + r.y * r.y + r.z * r.z + r.w * r.w;
    __shared__ float sh0[8], sh1[8];
    float ws = warp_sum(s), ws2 = warp_sum(s2);
    int wid = threadIdx.x >> 5, lid = threadIdx.x & 31;
    if (!lid) { sh0[wid] = ws; sh1[wid] = ws2; }
    __syncthreads();
    if (threadIdx.x == 0) {
        float a = 0.f, b = 0.f;
        #pragma unroll
        for (int k = 0; k < 8; k++) { a += sh0[k]; b += sh1[k]; }
        g_part[blockIdx.x] = make_float2(a, b);
    }
}

// ================= attention HMMA mainloop (3-stage, 1 sync/iter) =================
struct HmmaAcc { float a[4][4][4]; };

__device__ __forceinline__ void hmma_mainloop(
    HmmaAcc& A4, uint32_t sm0, int tid,
    const ushort_t* __restrict__ Ah, int lda,
    const ushort_t* __restrict__ Bh, int ldb,
    int m0, int n0, int kiters) {
    const int lane = tid & 31, warp = tid >> 5;
    const int wm = warp & 1, wn = warp >> 1;

    auto issue = [&](int stage, int k0) {
        uint32_t sb = sm0 + stage * STG;
        #pragma unroll
        for (int h = 0; h < 2; h++) {
            int id = tid + h * 256;
            int r = id >> 2, cu = id & 3;
            uint32_t soff = r * 64 + (((cu ^ ((r >> 1) & 3))) << 4);
            CP_ASYNC16(sb + soff,        Ah + (size_t)(m0 + r) * lda + k0 + cu * 8);
            CP_ASYNC16(sb + 8192 + soff, Bh + (size_t)(n0 + r) * ldb + k0 + cu * 8);
        }
        CP_COMMIT();
    };

    issue(0, 0);
    issue(1, 32);

    const int rl = lane & 15, ul = lane >> 4;
    for (int it = 0; it < kiters; it++) {
        CP_WAIT1();
        __syncthreads();
        if (it + 2 < kiters) issue((it + 2) % 3, (it + 2) * 32);
        else CP_COMMIT();
        uint32_t sb = sm0 + (it % 3) * STG;
        #pragma unroll
        for (int k16 = 0; k16 < 2; k16++) {
            uint32_t a4[4][4], b4[2][4];
            int u = k16 * 2 + ul;
            #pragma unroll
            for (int i = 0; i < 4; i++) {
                int r = wm * 64 + i * 16 + rl;
                LDSM4(a4[i], sb + r * 64 + (((u ^ ((r >> 1) & 3))) << 4));
            }
            #pragma unroll
            for (int j2 = 0; j2 < 2; j2++) {
                int r = wn * 32 + j2 * 16 + rl;
                LDSM4(b4[j2], sb + 8192 + r * 64 + (((u ^ ((r >> 1) & 3))) << 4));
            }
            #pragma unroll
            for (int i = 0; i < 4; i++)
                #pragma unroll
                for (int j = 0; j < 4; j++) {
                    int j2 = j >> 1, ts = j & 1;
                    MMA16816(A4.a[i][j], a4[i], b4[j2][ts], b4[j2][ts + 2]);
                }
        }
    }
}

// ---------------- conv GEMM: implicit gather, split-K, 4-stage, occ2 ----------
// grid (16, 64): x -> m-tile (x&3), ksplit (x>>2); y -> n-tile. 256 threads.
__global__ void __launch_bounds__(256, 2) conv_hmma_k() {
    extern __shared__ unsigned char dynsm[];
    const uint32_t sm0 = smem_u32(dynsm);
    const int tid = threadIdx.x, lane = tid & 31, warp = tid >> 5;
    const int m0 = (blockIdx.x & 3) * 128;
    const int ks = blockIdx.x >> 2;
    const int n0 = blockIdx.y * 128;
    const int kbase = ks * (KSPLIT_ITERS * 32);
    const int wm = warp & 1, wn = warp >> 1;

    int rrow[2], cu8[2];
    uint32_t soffv[2];
    int tm2[2], ym1[2], xm1[2];
    #pragma unroll
    for (int h = 0; h < 2; h++) {
        int id = tid + h * 256;
        int r = id >> 2, cu = id & 3;
        rrow[h] = r; cu8[h] = cu * 8;
        soffv[h] = r * 64 + (((cu ^ ((r >> 1) & 3))) << 4);
        int pos = n0 + r;
        tm2[h] = (pos >> 10) - 2;
        ym1[h] = ((pos >> 5) & 31) - 1;
        xm1[h] = (pos & 31) - 1;
    }

    auto issue = [&](int stage, int k0) {
        uint32_t sb = sm0 + stage * STG;
        int rcode = k0 >> 9;
        int ci0 = k0 & 511;
        int kd = rcode / 9;
        int rr = rcode - kd * 9;
        int kh = rr / 3;
        int kw = rr - kh * 3;
        #pragma unroll
        for (int h = 0; h < 2; h++) {
            CP_ASYNC16(sb + soffv[h],
                       g_wh + (size_t)(m0 + rrow[h]) * KC + k0 + cu8[h]);
            int ts = min(max(tm2[h] + kd, 0), 7);
            int ys = min(max(ym1[h] + kh, 0), 31);
            int xs = min(max(xm1[h] + kw, 0), 31);
            CP_ASYNC16(sb + 8192 + soffv[h],
                       g_ath + (size_t)((ts << 10) + (ys << 5) + xs) * C_ + ci0 + cu8[h]);
        }
        CP_COMMIT();
    };

    float acc[4][4][4];
    #pragma unroll
    for (int i = 0; i < 4; i++)
        #pragma unroll
        for (int j = 0; j < 4; j++)
            #pragma unroll
            for (int r = 0; r < 4; r++) acc[i][j][r] = 0.f;

    issue(0, kbase);
    issue(1, kbase + 32);
    issue(2, kbase + 64);

    const int rl = lane & 15, ul = lane >> 4;
    for (int it = 0; it < KSPLIT_ITERS; it++) {
        CP_WAIT2();
        __syncthreads();
        if (it + 3 < KSPLIT_ITERS) issue((it + 3) & 3, kbase + (it + 3) * 32);
        else CP_COMMIT();
        uint32_t sb = sm0 + (it & 3) * STG;
        #pragma unroll
        for (int k16 = 0; k16 < 2; k16++) {
            uint32_t a4[4][4], b4[2][4];
            int u = k16 * 2 + ul;
            #pragma unroll
            for (int i = 0; i < 4; i++) {
                int r = wm * 64 + i * 16 + rl;
                LDSM4(a4[i], sb + r * 64 + (((u ^ ((r >> 1) & 3))) << 4));
            }
            #pragma unroll
            for (int j2 = 0; j2 < 2; j2++) {
                int r = wn * 32 + j2 * 16 + rl;
                LDSM4(b4[j2], sb + 8192 + r * 64 + (((u ^ ((r >> 1) & 3))) << 4));
            }
            #pragma unroll
            for (int i = 0; i < 4; i++)
                #pragma unroll
                for (int j = 0; j < 4; j++) {
                    int j2 = j >> 1, ts = j & 1;
                    MMA16816(acc[i][j], a4[i], b4[j2][ts], b4[j2][ts + 2]);
                }
        }
    }

    float* Sp = g_ks + (size_t)ks * C_ * S_;
    const int mrow = m0 + wm * 64 + (lane >> 2);
    const int ncol = n0 + wn * 32 + (lane & 3) * 2;
    #pragma unroll
    for (int i = 0; i < 4; i++) {
        int ma = mrow + i * 16, mb = ma + 8;
        #pragma unroll
        for (int j = 0; j < 4; j++) {
            int n = ncol + j * 8;
            *(float2*)(Sp + (size_t)ma * S_ + n) = make_float2(acc[i][j][0], acc[i][j][1]);
            *(float2*)(Sp + (size_t)mb * S_ + n) = make_float2(acc[i][j][2], acc[i][j][3]);
        }
    }
}

// ---------------- generic attention GEMM, occ2 ----------------
// biasN2: bias for n-tiles with n0 >= 512 (merged QK projection)
__global__ void __launch_bounds__(256, 2) hmma_gemm_k(
    const ushort_t* __restrict__ Ah, int lda,
    const ushort_t* __restrict__ Bh, int ldb,
    float* __restrict__ Cf, ushort_t* __restrict__ Ch,
    int ldc, int K, float alpha,
    const float* __restrict__ biasM, const float* __restrict__ biasN,
    const float* __restrict__ biasN2,
    const float* __restrict__ addend, int causal, int kcausal, int mrev) {
    const int by = mrev ? (gridDim.y - 1 - blockIdx.y) : blockIdx.y;
    const int m0 = by * 128, n0 = blockIdx.x * 128;
    if (causal && n0 >= (((m0 >> 10) + 1) << 10)) return;
    int Keff = kcausal ? (((m0 >> 10) + 1) << 10) : K;
    int noff = 0;
    if (biasN2 && n0 >= 512) { biasN = biasN2; noff = 512; }

    extern __shared__ unsigned char dynsm[];
    const uint32_t sm0 = smem_u32(dynsm);
    const int tid = threadIdx.x, lane = tid & 31, warp = tid >> 5;
    const int wm = warp & 1, wn = warp >> 1;

    HmmaAcc acc;
    #pragma unroll
    for (int i = 0; i < 4; i++)
        #pragma unroll
        for (int j = 0; j < 4; j++)
            #pragma unroll
            for (int r = 0; r < 4; r++) acc.a[i][j][r] = 0.f;

    hmma_mainloop(acc, sm0, tid, Ah, lda, Bh, ldb, m0, n0, Keff >> 5);

    const int mrow = m0 + wm * 64 + (lane >> 2);
    const int ncol = n0 + wn * 32 + (lane & 3) * 2;
    #pragma unroll
    for (int i = 0; i < 4; i++) {
        int ma = mrow + i * 16, mb = ma + 8;
        float bva = biasM ? biasM[ma] : 0.f;
        float bvb = biasM ? biasM[mb] : 0.f;
        #pragma unroll
        for (int j = 0; j < 4; j++) {
            int n = ncol + j * 8;
            float2 va = make_float2(acc.a[i][j][0] * alpha + bva, acc.a[i][j][1] * alpha + bva);
            float2 vb = make_float2(acc.a[i][j][2] * alpha + bvb, acc.a[i][j][3] * alpha + bvb);
            if (biasN) {
                float b0 = biasN[n - noff], b1 = biasN[n + 1 - noff];
                va.x += b0; va.y += b1; vb.x += b0; vb.y += b1;
            }
            if (addend) {
                float2 aa = *(const float2*)(addend + (size_t)ma * ldc + n);
                float2 ab = *(const float2*)(addend + (size_t)mb * ldc + n);
                va.x += aa.x; va.y += aa.y; vb.x += ab.x; vb.y += ab.y;
            }
            if (Cf) {
                *(float2*)(Cf + (size_t)ma * ldc + n) = va;
                *(float2*)(Cf + (size_t)mb * ldc + n) = vb;
            }
            if (Ch) {
                *(ushort2*)(Ch + (size_t)ma * ldc + n) = make_ushort2(to_h(va.x), to_h(va.y));
                *(ushort2*)(Ch + (size_t)mb * ldc + n) = make_ushort2(to_h(vb.x), to_h(vb.y));
            }
        }
    }
}

// ---------------- softmax: fp16 scores in g_ph -> fp16 probs in place ----------
__global__ void softmax_k() {
    __shared__ float row[S_];
    __shared__ float sh[8];
    int i = (S_ - 1) - blockIdx.x;
    int L = ((i >> 10) + 1) << 10;
    ushort_t* rp = g_ph + ((size_t)i << 13);
    int n4 = L >> 2;
    int tid = threadIdx.x;

    float mx = -1e30f;
    for (int j = tid; j < n4; j += 256) {
        uint2 hv = *(const uint2*)(rp + 4 * (size_t)j);
        float2 f0 = __half22float2(*(__half2*)&hv.x);
        float2 f1 = __half22float2(*(__half2*)&hv.y);
        row[4 * j + 0] = f0.x; row[4 * j + 1] = f0.y;
        row[4 * j + 2] = f1.x; row[4 * j + 3] = f1.y;
        mx = fmaxf(mx, fmaxf(fmaxf(f0.x, f0.y), fmaxf(f1.x, f1.y)));
    }
    float wm = warp_max(mx);
    if ((tid & 31) == 0) sh[tid >> 5] = wm;
    __syncthreads();
    if (tid < 32) {
        float m2 = (tid < 8) ? sh[tid] : -1e30f;
        m2 = warp_max(m2);
        if (tid == 0) sh[0] = m2;
    }
    __syncthreads();
    float m = sh[0];
    __syncthreads();

    float s = 0.f;
    for (int j = tid; j < n4; j += 256) {
        float4 v = *(float4*)(row + 4 * j);
        v.x = __expf(v.x - m); v.y = __expf(v.y - m);
        v.z = __expf(v.z - m); v.w = __expf(v.w - m);
        s += v.x + v.y + v.z + v.w;
        *(float4*)(row + 4 * j) = v;
    }
    float ws = warp_sum(s);
    if ((tid & 31) == 0) sh[tid >> 5] = ws;
    __syncthreads();
    if (tid < 32) {
        float s2 = (tid < 8) ? sh[tid] : 0.f;
        s2 = warp_sum(s2);
        if (tid == 0) sh[0] = s2;
    }
    __syncthreads();
    float inv = 1.f / sh[0];
    for (int j = tid; j < n4; j += 256) {
        float4 v = *(float4*)(row + 4 * j);
        uint2 hv = make_uint2(
            (uint32_t)to_h(v.x * inv) | ((uint32_t)to_h(v.y * inv) << 16),
            (uint32_t)to_h(v.z * inv) | ((uint32_t)to_h(v.w * inv) << 16));
        *(uint2*)(rp + 4 * (size_t)j) = hv;
    }
}

// ---------------- orchestration ----------------
extern "C" void kernel_launch(void* const* d_in, const int* in_sizes, int n_in,
                              void* d_out, int out_size) {
    (void)in_sizes; (void)n_in; (void)out_size;

    float *t1, *y0, *mid;
    float2 *partp;
    ushort_t *wah, *woh, *wqk, *acth, *qkh, *vh, *oh, *ph;
    cudaGetSymbolAddress((void**)&t1,   g_t1);
    cudaGetSymbolAddress((void**)&y0,   g_y0);
    cudaGetSymbolAddress((void**)&mid,  g_mid);
    cudaGetSymbolAddress((void**)&partp, g_part);
    cudaGetSymbolAddress((void**)&wah,  g_wah);
    cudaGetSymbolAddress((void**)&woh,  g_woh);
    cudaGetSymbolAddress((void**)&wqk,  g_wqk);
    cudaGetSymbolAddress((void**)&acth, g_ath);
    cudaGetSymbolAddress((void**)&qkh,  g_qkh);
    cudaGetSymbolAddress((void**)&vh,   g_vh);
    cudaGetSymbolAddress((void**)&oh,   g_oh);
    cudaGetSymbolAddress((void**)&ph,   g_ph);

    cudaFuncSetAttribute(conv_hmma_k, cudaFuncAttributeMaxDynamicSharedMemorySize, 4 * STG);
    cudaFuncSetAttribute(hmma_gemm_k, cudaFuncAttributeMaxDynamicSharedMemorySize, 3 * STG);
    cudaFuncSetAttribute(wpack_conv_k, cudaFuncAttributeMaxDynamicSharedMemorySize, KC * 4);

    const float* X = (const float*)d_in[0];
    const float* a_gns = (const float*)d_in[17];
    const float* a_gnb = (const float*)d_in[18];
    const float* a_wq  = (const float*)d_in[19];
    const float* a_bq  = (const float*)d_in[20];
    const float* a_wk  = (const float*)d_in[21];
    const float* a_bk  = (const float*)d_in[22];
    const float* a_wv  = (const float*)d_in[23];
    const float* a_bv  = (const float*)d_in[24];
    const float* a_wo  = (const float*)d_in[25];
    const float* a_bo  = (const float*)d_in[26];

    const dim3 conv_grid(16, 64);
    const dim3 nt_grid(S_ / 32, C_ / 32);
    const dim3 nt_blk(32, 8);

    auto resnet = [&](const float* in, int base, float* midb, float* outbuf) {
        const float* n1s = (const float*)d_in[base + 0];
        const float* n1b = (const float*)d_in[base + 1];
        const float* w1  = (const float*)d_in[base + 2];
        const float* b1  = (const float*)d_in[base + 3];
        const float* n2s = (const float*)d_in[base + 4];
        const float* n2b = (const float*)d_in[base + 5];
        const float* w2  = (const float*)d_in[base + 6];
        const float* b2  = (const float*)d_in[base + 7];

        gn_stats_k<<<NGROUP, 256>>>(in);
        normact_t_k<<<nt_grid, nt_blk>>>(in, n1s, n1b, 1, nullptr);
        wpack_conv_k<<<C_, 256, KC * 4>>>(w1);
        conv_hmma_k<<<conv_grid, 256, 4 * STG>>>();
        ksum_k<<<KSUM_BLOCKS, 256>>>(midb, b1, nullptr);
        normact_t_k<<<nt_grid, nt_blk>>>(midb, n2s, n2b, 1, partp);
        wpack_conv_k<<<C_, 256, KC * 4>>>(w2);
        conv_hmma_k<<<conv_grid, 256, 4 * STG>>>();
        ksum_k<<<KSUM_BLOCKS, 256>>>(outbuf, b2, in);
    };

    // ---- ResNet block 0:  X -> y0 ----
    resnet(X, 1, t1, y0);

    // ---- Causal frame attention on y0 (stats via ksum partials, inline) ----
    normact_t_k<<<nt_grid, nt_blk>>>(y0, a_gns, a_gnb, 0, partp);
    wpack_all_k<<<dim3(128, 4), 256>>>(a_wq, a_wk, a_wv, a_wo);

    // QK merged: C[s][0..1023] = act . (wq||wk)^T + (bq||bk)
    hmma_gemm_k<<<dim3(8, 64), 256, 3 * STG>>>(acth, C_, wqk, C_,
        nullptr, qkh, 1024, C_, 1.f, nullptr, a_bq, a_bk, nullptr, 0, 0, 0);
    // V[d][s] = wv . act^T + bv
    hmma_gemm_k<<<dim3(64, 4), 256, 3 * STG>>>(wah, C_, acth, C_,
        nullptr, vh, S_, C_, 1.f, a_bv, nullptr, nullptr, nullptr, 0, 0, 0);

    // scores (fp16 out): Q . K^T  (Q = qkh cols 0-511, K = qkh cols 512-1023)
    hmma_gemm_k<<<dim3(64, 64), 256, 3 * STG>>>(qkh, 1024, qkh + 512, 1024,
        nullptr, ph, S_, C_, 0.04419417382415922f,
        nullptr, nullptr, nullptr, nullptr, 1, 0, 0);
    softmax_k<<<S_, 256>>>();
    // O[s][d] = P . V^T  (reversed m-order, causal K bound)
    hmma_gemm_k<<<dim3(4, 64), 256, 3 * STG>>>(ph, S_, vh, S_,
        nullptr, oh, C_, S_, 1.f, nullptr, nullptr, nullptr, nullptr, 0, 1, 1);
    // attnout[c][s] = wo . O^T + bo + y0
    hmma_gemm_k<<<dim3(64, 4), 256, 3 * STG>>>(woh, C_, oh, C_,
        t1, nullptr, S_, C_, 1.f, a_bo, nullptr, nullptr, y0, 0, 0, 0);

    // ---- ResNet block 1:  t1 -> d_out ----
    resnet(t1, 9, mid, (float*)d_out);
}